// round 14
// baseline (speedup 1.0000x reference)
#include <cuda_runtime.h>
#include <cuda_fp16.h>

#define NN 100000
#define NE 200000
#define NG 5000
static constexpr float EPSV = 1e-5f;

// ---------------- device scratch ----------------
__device__ __align__(16) __half g_T1[(size_t)NN * 128];   // [n][f*16+i] fp16
__device__ __align__(16) __half g_T2[(size_t)NN * 256];   // [n][f*32+i] fp16
__device__ __align__(16) float g_h1 [NN * 32];
__device__ __align__(16) __half g_h1nh[NN * 32];          // fp16 h1n (only copy)
__device__ __align__(16) __half g_h2h[NN * 64];           // fp16 h2
__device__ __align__(16) float g_pooled[NG * 64];
__device__ float g_cnt[NG];
__device__ int   g_deg[NN];      // out-degree (norm)
__device__ int   g_indeg[NN];    // in-degree (CSR)
__device__ int   g_off[NN];
__device__ int   g_cur[NN];
__device__ int   g_bsum[128];
__device__ int   g_src[NE];
__device__ __align__(16) __half g_eaz[(size_t)NE * 8];    // ea*nrm fp16, dst-sorted
__device__ float g_stat1[64];
__device__ float g_stat2[128];
__device__ __align__(16) float g_W1p[128 * 32];    // [k=f*16+i][o]
__device__ __align__(16) float g_W2p[256 * 64];    // [k=f*32+i][o]
__device__ __align__(16) float g_Wt1[64 * 128];
__device__ __align__(16) float g_Wt2[128 * 128];

__device__ __forceinline__ void red_v4(float* p, float4 v) {
    asm volatile("red.global.add.v4.f32 [%0], {%1,%2,%3,%4};"
                 :: "l"(p), "f"(v.x), "f"(v.y), "f"(v.z), "f"(v.w) : "memory");
}

__device__ __forceinline__ uint2 pack4h(float a, float b, float c, float d) {
    __half2 p0 = __floats2half2_rn(a, b);
    __half2 p1 = __floats2half2_rn(c, d);
    uint2 u;
    u.x = *(unsigned*)&p0;
    u.y = *(unsigned*)&p1;
    return u;
}
__device__ __forceinline__ float4 unpack4h(uint2 u) {
    __half2 h0 = *(__half2*)&u.x;
    __half2 h1 = *(__half2*)&u.y;
    float2 f0 = __half22float2(h0);
    float2 f1 = __half22float2(h1);
    return make_float4(f0.x, f0.y, f1.x, f1.y);
}

// ---------------- setup: init accumulators + weight prep (merged) ----------
__global__ void k_setup(const float* __restrict__ We1, const float* __restrict__ We2,
                        const float* __restrict__ Wf1, const float* __restrict__ Wf2) {
    int idx = blockIdx.x * blockDim.x + threadIdx.x;
    int stride = gridDim.x * blockDim.x;
    for (int j = idx; j < NG * 64; j += stride) g_pooled[j] = 0.f;
    for (int j = idx; j < NG;      j += stride) g_cnt[j] = 0.f;
    for (int j = idx; j < NN;      j += stride) { g_deg[j] = 0; g_indeg[j] = 0; }
    if (idx < 64)  g_stat1[idx] = 0.f;
    if (idx < 128) g_stat2[idx] = 0.f;

    if (idx < 128 * 32) {
        int k = idx >> 5, o = idx & 31;
        int f = k >> 4, i = k & 15;
        g_W1p[idx] = We1[((o << 4) + i) * 8 + f];
    }
    int j = idx - 128 * 32;
    if (j >= 0 && j < 256 * 64) {
        int k = j >> 6, o = j & 63;
        int f = k >> 5, i = k & 31;
        g_W2p[j] = We2[((o << 5) + i) * 8 + f];
    }
    int p = idx - (128 * 32 + 256 * 64);
    if (p >= 0 && p < 64 * 128) {
        int i = p >> 7, o = p & 127;
        g_Wt1[p] = Wf1[o * 64 + i];
    }
    int q = idx - (128 * 32 + 256 * 64 + 64 * 128);
    if (q >= 0 && q < 128 * 128) {
        int i = q >> 7, o = q & 127;
        g_Wt2[q] = Wf2[o * 128 + i];
    }
}

// ---------------- degree counts ----------------
__global__ void k_degs(const int* __restrict__ ei) {
    int e = blockIdx.x * blockDim.x + threadIdx.x;
    if (e < NE) {
        atomicAdd(&g_deg[ei[e]], 1);
        atomicAdd(&g_indeg[ei[NE + e]], 1);
    }
}

// ---------------- scan (2 kernels) ----------------
#define SCAN_NB 98
__global__ void k_scan_a() {
    __shared__ int ss[256];
    int b = blockIdx.x, t = threadIdx.x;
    int base = b * 1024 + t * 4;
    int s = 0;
    #pragma unroll
    for (int c = 0; c < 4; c++) { int i = base + c; if (i < NN) s += g_indeg[i]; }
    ss[t] = s; __syncthreads();
    for (int off = 128; off >= 1; off >>= 1) {
        if (t < off) ss[t] += ss[t + off];
        __syncthreads();
    }
    if (t == 0) g_bsum[b] = ss[0];
}
__global__ void k_scan_c() {
    __shared__ int ss[256];
    __shared__ int sbl[SCAN_NB];
    __shared__ int sboff;
    int b = blockIdx.x, t = threadIdx.x;
    if (t < SCAN_NB) sbl[t] = g_bsum[t];
    __syncthreads();
    if (t == 0) {
        int run = 0;
        for (int i = 0; i < b; i++) run += sbl[i];
        sboff = run;
    }
    int base = b * 1024 + t * 4;
    int v[4]; int s = 0;
    #pragma unroll
    for (int c = 0; c < 4; c++) { int i = base + c; v[c] = (i < NN) ? g_indeg[i] : 0; s += v[c]; }
    ss[t] = s; __syncthreads();
    for (int off = 1; off < 256; off <<= 1) {
        int add = (t >= off) ? ss[t - off] : 0;
        __syncthreads();
        ss[t] += add;
        __syncthreads();
    }
    int run = sboff + ss[t] - s;   // exclusive prefix
    #pragma unroll
    for (int c = 0; c < 4; c++) {
        int i = base + c;
        if (i < NN) { g_off[i] = run; g_cur[i] = run; run += v[c]; }
    }
}

// ---------------- fill (fp16 eaz) ----------------
__global__ void k_fill(const int* __restrict__ ei, const float* __restrict__ ea) {
    int e = blockIdx.x * blockDim.x + threadIdx.x;
    if (e >= NE) return;
    int s = ei[e], d = ei[NE + e];
    float nrm = 1.0f / (float)g_deg[s];
    int pos = atomicAdd(&g_cur[d], 1);
    g_src[pos] = s;
    float4 a0 = __ldg((const float4*)(ea + (size_t)e * 8));
    float4 a1 = __ldg((const float4*)(ea + (size_t)e * 8 + 4));
    uint2 u0 = pack4h(a0.x * nrm, a0.y * nrm, a0.z * nrm, a0.w * nrm);
    uint2 u1 = pack4h(a1.x * nrm, a1.y * nrm, a1.z * nrm, a1.w * nrm);
    uint4 u;
    u.x = u0.x; u.y = u0.y; u.z = u1.x; u.w = u1.y;
    *(uint4*)(g_eaz + (size_t)pos * 8) = u;
}

__device__ __forceinline__ void load_eaz8(int pos, float* ef) {
    uint4 u = __ldg((const uint4*)(g_eaz + (size_t)pos * 8));
    float4 lo = unpack4h(make_uint2(u.x, u.y));
    float4 hi = unpack4h(make_uint2(u.z, u.w));
    ef[0] = lo.x; ef[1] = lo.y; ef[2] = lo.z; ef[3] = lo.w;
    ef[4] = hi.x; ef[5] = hi.y; ef[6] = hi.z; ef[7] = hi.w;
}

// ---------------- gather build T1: 4 threads per node (fp16 out) ------------
__global__ __launch_bounds__(256) void k_gath1(const float* __restrict__ x) {
    int tid = blockIdx.x * 256 + threadIdx.x;
    int gn = tid >> 2, j = tid & 3;
    if (gn >= NN) return;
    float acc[32];
    #pragma unroll
    for (int q = 0; q < 32; q++) acc[q] = 0.f;
    int start = g_off[gn], cnt = g_indeg[gn];
    for (int q = 0; q < cnt; q++) {
        int pos = start + q;
        int s = __ldg(g_src + pos);
        float4 xv = __ldg((const float4*)(x + (size_t)s * 16 + j * 4));
        float ef[8];
        load_eaz8(pos, ef);
        #pragma unroll
        for (int f = 0; f < 8; f++) {
            acc[f * 4 + 0] += ef[f] * xv.x;
            acc[f * 4 + 1] += ef[f] * xv.y;
            acc[f * 4 + 2] += ef[f] * xv.z;
            acc[f * 4 + 3] += ef[f] * xv.w;
        }
    }
    __half* dst = g_T1 + (size_t)gn * 128 + j * 4;
    #pragma unroll
    for (int f = 0; f < 8; f++)
        *(uint2*)(dst + f * 16) = pack4h(acc[f * 4], acc[f * 4 + 1],
                                         acc[f * 4 + 2], acc[f * 4 + 3]);
}

// ---------------- gather build T2: 8 threads per node (fp16 in/out) ---------
__global__ __launch_bounds__(256) void k_gath2() {
    int tid = blockIdx.x * 256 + threadIdx.x;
    int gn = tid >> 3, j = tid & 7;
    if (gn >= NN) return;
    float acc[32];
    #pragma unroll
    for (int q = 0; q < 32; q++) acc[q] = 0.f;
    int start = g_off[gn], cnt = g_indeg[gn];
    for (int q = 0; q < cnt; q++) {
        int pos = start + q;
        int s = __ldg(g_src + pos);
        uint2 hraw = __ldg((const uint2*)(g_h1nh + (size_t)s * 32 + j * 4));
        float4 hv = unpack4h(hraw);
        float ef[8];
        load_eaz8(pos, ef);
        #pragma unroll
        for (int f = 0; f < 8; f++) {
            acc[f * 4 + 0] += ef[f] * hv.x;
            acc[f * 4 + 1] += ef[f] * hv.y;
            acc[f * 4 + 2] += ef[f] * hv.z;
            acc[f * 4 + 3] += ef[f] * hv.w;
        }
    }
    __half* dst = g_T2 + (size_t)gn * 256 + j * 4;
    #pragma unroll
    for (int f = 0; f < 8; f++)
        *(uint2*)(dst + f * 32) = pack4h(acc[f * 4], acc[f * 4 + 1],
                                         acc[f * 4 + 2], acc[f * 4 + 3]);
}

// ---------------- GEMM layer1: double-buffered, fp16 T1 loads ---------------
__global__ __launch_bounds__(128) void k_gemm_l1(const float* __restrict__ x,
                                                 const float* __restrict__ Wr1,
                                                 const float* __restrict__ b1) {
    __shared__ float As[2][32 * 132];
    __shared__ float Bs[2][32 * 32];
    __shared__ float s_sum[32], s_sq[32];
    int tid = threadIdx.x;
    if (tid < 32) { s_sum[tid] = 0.f; s_sq[tid] = 0.f; }
    int n0 = blockIdx.x * 128;
    int tn = tid >> 3, to = tid & 7;
    int kq = tid & 7, rr = tid >> 3;

    float acc[8][4];
    #pragma unroll
    for (int m = 0; m < 8; m++)
        #pragma unroll
        for (int c = 0; c < 4; c++) acc[m][c] = 0.f;

    float4 pa[8];
    float  pb[8];

    auto load_stage = [&](int s) {
        #pragma unroll
        for (int it = 0; it < 8; it++) {
            int row = it * 16 + rr;
            int gn = n0 + row;
            float4 v = make_float4(0.f, 0.f, 0.f, 0.f);
            if (gn < NN) {
                if (s < 4) {
                    uint2 raw = __ldg((const uint2*)(g_T1 + (size_t)gn * 128 + s * 32 + kq * 4));
                    v = unpack4h(raw);
                } else if (kq < 4) {
                    v = *(const float4*)(x + (size_t)gn * 16 + kq * 4);
                }
            }
            pa[it] = v;
        }
        #pragma unroll
        for (int i = 0; i < 8; i++) {
            int t = i * 128 + tid;
            float w = 0.f;
            if (s < 4) w = g_W1p[s * 1024 + t];
            else { int k = t >> 5, o = t & 31; if (k < 16) w = Wr1[o * 16 + k]; }
            pb[i] = w;
        }
    };
    auto store_stage = [&](int b) {
        #pragma unroll
        for (int it = 0; it < 8; it++) {
            int row = it * 16 + rr;
            As[b][(kq * 4 + 0) * 132 + row] = pa[it].x;
            As[b][(kq * 4 + 1) * 132 + row] = pa[it].y;
            As[b][(kq * 4 + 2) * 132 + row] = pa[it].z;
            As[b][(kq * 4 + 3) * 132 + row] = pa[it].w;
        }
        #pragma unroll
        for (int i = 0; i < 8; i++) Bs[b][i * 128 + tid] = pb[i];
    };

    load_stage(0);
    store_stage(0);
    __syncthreads();

    for (int s = 0; s < 5; s++) {
        int buf = s & 1;
        if (s < 4) load_stage(s + 1);
        const float* Ab = As[buf];
        const float* Bb = Bs[buf];
        #pragma unroll
        for (int k = 0; k < 32; k++) {
            float4 b = *(const float4*)(Bb + k * 32 + to * 4);
            float4 a0 = *(const float4*)(Ab + k * 132 + tn * 8);
            float4 a1 = *(const float4*)(Ab + k * 132 + tn * 8 + 4);
            const float av[8] = {a0.x, a0.y, a0.z, a0.w, a1.x, a1.y, a1.z, a1.w};
            #pragma unroll
            for (int m = 0; m < 8; m++) {
                acc[m][0] += av[m] * b.x; acc[m][1] += av[m] * b.y;
                acc[m][2] += av[m] * b.z; acc[m][3] += av[m] * b.w;
            }
        }
        if (s < 4) store_stage(buf ^ 1);
        __syncthreads();
    }

    float bv[4];
    #pragma unroll
    for (int c = 0; c < 4; c++) bv[c] = __ldg(b1 + to * 4 + c);
    float ls[4] = {0, 0, 0, 0}, lq[4] = {0, 0, 0, 0};
    #pragma unroll
    for (int m = 0; m < 8; m++) {
        int gn = n0 + tn * 8 + m;
        if (gn < NN) {
            float4 h;
            h.x = acc[m][0] + bv[0]; h.y = acc[m][1] + bv[1];
            h.z = acc[m][2] + bv[2]; h.w = acc[m][3] + bv[3];
            *(float4*)(g_h1 + (size_t)gn * 32 + to * 4) = h;
            ls[0] += h.x; ls[1] += h.y; ls[2] += h.z; ls[3] += h.w;
            lq[0] += h.x * h.x; lq[1] += h.y * h.y; lq[2] += h.z * h.z; lq[3] += h.w * h.w;
        }
    }
    #pragma unroll
    for (int c = 0; c < 4; c++) {
        atomicAdd(&s_sum[to * 4 + c], ls[c]);
        atomicAdd(&s_sq [to * 4 + c], lq[c]);
    }
    __syncthreads();
    if (tid < 32) {
        atomicAdd(&g_stat1[tid],      s_sum[tid]);
        atomicAdd(&g_stat1[32 + tid], s_sq[tid]);
    }
}

// ---------------- GEMM layer2: 128 thr, 8x8 thread tile, fp16 A -------------
// tile 128n x 64o; 9 uniform K=32 stages (8x T2 fp16, 1x aux h1nh/Wr2^T).
#define L2G_SMEM ((2 * 32 * 132 + 2 * 32 * 64) * 4)
__global__ __launch_bounds__(128) void k_gemm_l2(const float* __restrict__ Wr2,
                                                 const float* __restrict__ b2) {
    extern __shared__ float sml2[];
    float* As0 = sml2;
    float* As1 = As0 + 32 * 132;
    float* Bs0 = As1 + 32 * 132;
    float* Bs1 = Bs0 + 32 * 64;
    __shared__ float s_sum[64], s_sq[64];
    int tid = threadIdx.x;
    if (tid < 64) { s_sum[tid] = 0.f; s_sq[tid] = 0.f; }
    int n0 = blockIdx.x * 128;
    int tn = tid >> 3, to = tid & 7;     // 16 x 8 thread grid, 8x8 tile
    int kq = tid & 7, rr = tid >> 3;

    float acc[8][8];
    #pragma unroll
    for (int m = 0; m < 8; m++)
        #pragma unroll
        for (int c = 0; c < 8; c++) acc[m][c] = 0.f;

    float4 pa[8];
    float  pb[16];

    auto load_stage = [&](int s) {
        #pragma unroll
        for (int it = 0; it < 8; it++) {
            int row = it * 16 + rr;
            int gn = n0 + row;
            float4 v = make_float4(0.f, 0.f, 0.f, 0.f);
            if (gn < NN) {
                const __half* src = (s < 8)
                    ? g_T2 + (size_t)gn * 256 + s * 32 + kq * 4
                    : g_h1nh + (size_t)gn * 32 + kq * 4;
                uint2 raw = __ldg((const uint2*)src);
                v = unpack4h(raw);
            }
            pa[it] = v;
        }
        #pragma unroll
        for (int i = 0; i < 16; i++) {
            int t = i * 128 + tid;
            float w;
            if (s < 8) w = g_W2p[s * 2048 + t];
            else { int k = t >> 6, o = t & 63; w = Wr2[o * 32 + k]; }
            pb[i] = w;
        }
    };
    auto store_stage = [&](float* Ab, float* Bb) {
        #pragma unroll
        for (int it = 0; it < 8; it++) {
            int row = it * 16 + rr;
            Ab[(kq * 4 + 0) * 132 + row] = pa[it].x;
            Ab[(kq * 4 + 1) * 132 + row] = pa[it].y;
            Ab[(kq * 4 + 2) * 132 + row] = pa[it].z;
            Ab[(kq * 4 + 3) * 132 + row] = pa[it].w;
        }
        #pragma unroll
        for (int i = 0; i < 16; i++) Bb[i * 128 + tid] = pb[i];
    };

    load_stage(0);
    store_stage(As0, Bs0);
    __syncthreads();

    for (int s = 0; s < 9; s++) {
        int buf = s & 1;
        if (s < 8) load_stage(s + 1);
        const float* Ab = buf ? As1 : As0;
        const float* Bb = buf ? Bs1 : Bs0;
        #pragma unroll
        for (int k = 0; k < 32; k++) {
            float4 b0 = *(const float4*)(Bb + k * 64 + to * 8);
            float4 b1 = *(const float4*)(Bb + k * 64 + to * 8 + 4);
            float4 a0 = *(const float4*)(Ab + k * 132 + tn * 8);
            float4 a1 = *(const float4*)(Ab + k * 132 + tn * 8 + 4);
            const float av[8] = {a0.x, a0.y, a0.z, a0.w, a1.x, a1.y, a1.z, a1.w};
            const float bv[8] = {b0.x, b0.y, b0.z, b0.w, b1.x, b1.y, b1.z, b1.w};
            #pragma unroll
            for (int m = 0; m < 8; m++)
                #pragma unroll
                for (int c = 0; c < 8; c++)
                    acc[m][c] += av[m] * bv[c];
        }
        if (s < 8) store_stage(buf ? As0 : As1, buf ? Bs0 : Bs1);
        __syncthreads();
    }

    float bv8[8];
    #pragma unroll
    for (int c = 0; c < 8; c++) bv8[c] = __ldg(b2 + to * 8 + c);
    float ls[8] = {0, 0, 0, 0, 0, 0, 0, 0}, lq[8] = {0, 0, 0, 0, 0, 0, 0, 0};
    #pragma unroll
    for (int m = 0; m < 8; m++) {
        int gn = n0 + tn * 8 + m;
        if (gn < NN) {
            float h[8];
            #pragma unroll
            for (int c = 0; c < 8; c++) {
                h[c] = acc[m][c] + bv8[c];
                ls[c] += h[c];
                lq[c] += h[c] * h[c];
            }
            *(uint2*)(g_h2h + (size_t)gn * 64 + to * 8)     = pack4h(h[0], h[1], h[2], h[3]);
            *(uint2*)(g_h2h + (size_t)gn * 64 + to * 8 + 4) = pack4h(h[4], h[5], h[6], h[7]);
        }
    }
    #pragma unroll
    for (int c = 0; c < 8; c++) {
        atomicAdd(&s_sum[to * 8 + c], ls[c]);
        atomicAdd(&s_sq [to * 8 + c], lq[c]);
    }
    __syncthreads();
    if (tid < 64) {
        atomicAdd(&g_stat2[tid],      s_sum[tid]);
        atomicAdd(&g_stat2[64 + tid], s_sq[tid]);
    }
}

// ---------------- BN1 apply + relu -> h1nh (fp16 only) ----------------
__global__ void k_bn1(const float* __restrict__ g1, const float* __restrict__ be1) {
    int idx = blockIdx.x * blockDim.x + threadIdx.x;
    if (idx >= NN * 8) return;
    int n = idx >> 3, q = idx & 7;
    const float invN = 1.0f / (float)NN;
    float4 h = *(const float4*)(g_h1 + (size_t)n * 32 + q * 4);
    float v[4];
    float* hv = (float*)&h;
    #pragma unroll
    for (int j = 0; j < 4; j++) {
        int c = q * 4 + j;
        float mu = g_stat1[c] * invN;
        float var = g_stat1[32 + c] * invN - mu * mu;
        float rs = rsqrtf(var + EPSV);
        v[j] = fmaxf((hv[j] - mu) * rs * __ldg(g1 + c) + __ldg(be1 + c), 0.f);
    }
    *(uint2*)(g_h1nh + (size_t)n * 32 + q * 4) = pack4h(v[0], v[1], v[2], v[3]);
}

// ---------------- BN2 apply + relu + pooling (node pairs, fp16 in) ----------
__global__ void k_bn2pool(const float* __restrict__ g2, const float* __restrict__ be2,
                          const int* __restrict__ batch) {
    int idx = blockIdx.x * blockDim.x + threadIdx.x;
    if (idx >= NN * 8) return;
    int np = idx >> 4, q = idx & 15;
    int n0 = np * 2, n1 = np * 2 + 1;
    const float invN = 1.0f / (float)NN;

    float4 hA = unpack4h(__ldg((const uint2*)(g_h2h + (size_t)n0 * 64 + q * 4)));
    float4 hB = unpack4h(__ldg((const uint2*)(g_h2h + (size_t)n1 * 64 + q * 4)));
    float vA[4], vB[4];
    float* ha = (float*)&hA; float* hb = (float*)&hB;
    #pragma unroll
    for (int j = 0; j < 4; j++) {
        int c = q * 4 + j;
        float mu = g_stat2[c] * invN;
        float var = g_stat2[64 + c] * invN - mu * mu;
        float rs = rsqrtf(var + EPSV);
        float ga = __ldg(g2 + c), ba = __ldg(be2 + c);
        vA[j] = fmaxf((ha[j] - mu) * rs * ga + ba, 0.f);
        vB[j] = fmaxf((hb[j] - mu) * rs * ga + ba, 0.f);
    }
    int b0 = batch[n0], b1 = batch[n1];
    if (b0 == b1) {
        red_v4(g_pooled + (size_t)b0 * 64 + q * 4,
               make_float4(vA[0] + vB[0], vA[1] + vB[1], vA[2] + vB[2], vA[3] + vB[3]));
        if (q == 0) atomicAdd(&g_cnt[b0], 2.0f);
    } else {
        red_v4(g_pooled + (size_t)b0 * 64 + q * 4, make_float4(vA[0], vA[1], vA[2], vA[3]));
        red_v4(g_pooled + (size_t)b1 * 64 + q * 4, make_float4(vB[0], vB[1], vB[2], vB[3]));
        if (q == 0) { atomicAdd(&g_cnt[b0], 1.0f); atomicAdd(&g_cnt[b1], 1.0f); }
    }
}

// ---------------- final MLP ----------------
__global__ __launch_bounds__(128) void k_fc(const float* __restrict__ bf1,
                                            const float* __restrict__ bf2,
                                            float* __restrict__ out) {
    __shared__ float pm[8][64];
    __shared__ float hid[8][128];
    int tid = threadIdx.x;
    int g0 = blockIdx.x * 8;
    for (int t = tid; t < 512; t += 128) {
        int gg = t >> 6, i = t & 63;
        int g = g0 + gg;
        pm[gg][i] = g_pooled[g * 64 + i] / fmaxf(g_cnt[g], 1.0f);
    }
    __syncthreads();

    float acc[8];
    float b = bf1[tid];
    #pragma unroll
    for (int gg = 0; gg < 8; gg++) acc[gg] = b;
    for (int i = 0; i < 64; i++) {
        float w = g_Wt1[i * 128 + tid];
        #pragma unroll
        for (int gg = 0; gg < 8; gg++) acc[gg] += w * pm[gg][i];
    }
    #pragma unroll
    for (int gg = 0; gg < 8; gg++) hid[gg][tid] = fmaxf(acc[gg], 0.f);
    __syncthreads();

    float b2v = bf2[tid];
    #pragma unroll
    for (int gg = 0; gg < 8; gg++) acc[gg] = b2v;
    for (int i = 0; i < 128; i++) {
        float w = g_Wt2[i * 128 + tid];
        #pragma unroll
        for (int gg = 0; gg < 8; gg++) acc[gg] += w * hid[gg][i];
    }
    #pragma unroll
    for (int gg = 0; gg < 8; gg++) {
        int g = g0 + gg;
        if (tid < 64) out[g * 64 + tid] = acc[gg];
        else          out[NG * 64 + g * 64 + (tid - 64)] = acc[gg];
    }
}

// ---------------- launch ----------------
extern "C" void kernel_launch(void* const* d_in, const int* in_sizes, int n_in,
                              void* d_out, int out_size) {
    const float* x    = (const float*)d_in[0];
    const int*   ei   = (const int*)  d_in[1];
    const float* ea   = (const float*)d_in[2];
    const int*   batch= (const int*)  d_in[3];
    const float* We1  = (const float*)d_in[4];
    const float* b1   = (const float*)d_in[5];
    const float* Wr1  = (const float*)d_in[6];
    const float* g1   = (const float*)d_in[7];
    const float* be1  = (const float*)d_in[8];
    const float* We2  = (const float*)d_in[9];
    const float* b2   = (const float*)d_in[10];
    const float* Wr2  = (const float*)d_in[11];
    const float* g2   = (const float*)d_in[12];
    const float* be2  = (const float*)d_in[13];
    const float* Wf1  = (const float*)d_in[14];
    const float* bf1  = (const float*)d_in[15];
    const float* Wf2  = (const float*)d_in[16];
    const float* bf2  = (const float*)d_in[17];
    float* out = (float*)d_out;

    static int attr_set = 0;
    if (!attr_set) {
        cudaFuncSetAttribute(k_gemm_l2, cudaFuncAttributeMaxDynamicSharedMemorySize,
                             L2G_SMEM);
        attr_set = 1;
    }

    k_setup<<<256, 256>>>(We1, We2, Wf1, Wf2);
    k_degs<<<(NE + 255) / 256, 256>>>(ei);
    k_scan_a<<<SCAN_NB, 256>>>();
    k_scan_c<<<SCAN_NB, 256>>>();
    k_fill<<<(NE + 255) / 256, 256>>>(ei, ea);
    k_gath1<<<(NN * 4 + 255) / 256, 256>>>(x);
    k_gemm_l1<<<(NN + 127) / 128, 128>>>(x, Wr1, b1);
    k_bn1<<<(NN * 8 + 255) / 256, 256>>>(g1, be1);
    k_gath2<<<(NN * 8 + 255) / 256, 256>>>();
    k_gemm_l2<<<(NN + 127) / 128, 128, L2G_SMEM>>>(Wr2, b2);
    k_bn2pool<<<(NN * 8 + 255) / 256, 256>>>(g2, be2, batch);
    k_fc<<<NG / 8, 128>>>(bf1, bf2, out);
}

// round 15
// speedup vs baseline: 1.0564x; 1.0564x over previous
#include <cuda_runtime.h>
#include <cuda_fp16.h>

#define NN 100000
#define NE 200000
#define NG 5000
static constexpr float EPSV = 1e-5f;

// ---------------- device scratch ----------------
__device__ __align__(16) __half g_T1[(size_t)NN * 128];   // [n][f*16+i] fp16
__device__ __align__(16) __half g_T2[(size_t)NN * 256];   // [n][f*32+i] fp16
__device__ __align__(16) __half g_h1h[NN * 32];           // fp16 h1 (pre-BN)
__device__ __align__(16) __half g_h1nh[NN * 32];          // fp16 h1n
__device__ __align__(16) __half g_h2h[NN * 64];           // fp16 h2
__device__ __align__(16) float g_pooled[NG * 64];
__device__ float g_cnt[NG];
__device__ int   g_deg[NN];      // out-degree (norm)
__device__ int   g_indeg[NN];    // in-degree (CSR)
__device__ int   g_off[NN];
__device__ int   g_cur[NN];
__device__ int   g_bsum[128];
__device__ int   g_src[NE];
__device__ __align__(16) __half g_eaz[(size_t)NE * 8];    // ea*nrm fp16, dst-sorted
__device__ float g_stat1[64];
__device__ float g_stat2[128];
__device__ __align__(16) float g_W1p[128 * 32];    // [k=f*16+i][o]
__device__ __align__(16) float g_W2p[256 * 64];    // [k=f*32+i][o]
__device__ __align__(16) float g_Wt1[64 * 128];
__device__ __align__(16) float g_Wt2[128 * 128];

__device__ __forceinline__ void red_v4(float* p, float4 v) {
    asm volatile("red.global.add.v4.f32 [%0], {%1,%2,%3,%4};"
                 :: "l"(p), "f"(v.x), "f"(v.y), "f"(v.z), "f"(v.w) : "memory");
}

__device__ __forceinline__ uint2 pack4h(float a, float b, float c, float d) {
    __half2 p0 = __floats2half2_rn(a, b);
    __half2 p1 = __floats2half2_rn(c, d);
    uint2 u;
    u.x = *(unsigned*)&p0;
    u.y = *(unsigned*)&p1;
    return u;
}
__device__ __forceinline__ float4 unpack4h(uint2 u) {
    __half2 h0 = *(__half2*)&u.x;
    __half2 h1 = *(__half2*)&u.y;
    float2 f0 = __half22float2(h0);
    float2 f1 = __half22float2(h1);
    return make_float4(f0.x, f0.y, f1.x, f1.y);
}

// ---------------- setup: init accumulators + weight prep (merged) ----------
__global__ void k_setup(const float* __restrict__ We1, const float* __restrict__ We2,
                        const float* __restrict__ Wf1, const float* __restrict__ Wf2) {
    int idx = blockIdx.x * blockDim.x + threadIdx.x;
    int stride = gridDim.x * blockDim.x;
    for (int j = idx; j < NG * 64; j += stride) g_pooled[j] = 0.f;
    for (int j = idx; j < NG;      j += stride) g_cnt[j] = 0.f;
    for (int j = idx; j < NN;      j += stride) { g_deg[j] = 0; g_indeg[j] = 0; }
    if (idx < 64)  g_stat1[idx] = 0.f;
    if (idx < 128) g_stat2[idx] = 0.f;

    if (idx < 128 * 32) {
        int k = idx >> 5, o = idx & 31;
        int f = k >> 4, i = k & 15;
        g_W1p[idx] = We1[((o << 4) + i) * 8 + f];
    }
    int j = idx - 128 * 32;
    if (j >= 0 && j < 256 * 64) {
        int k = j >> 6, o = j & 63;
        int f = k >> 5, i = k & 31;
        g_W2p[j] = We2[((o << 5) + i) * 8 + f];
    }
    int p = idx - (128 * 32 + 256 * 64);
    if (p >= 0 && p < 64 * 128) {
        int i = p >> 7, o = p & 127;
        g_Wt1[p] = Wf1[o * 64 + i];
    }
    int q = idx - (128 * 32 + 256 * 64 + 64 * 128);
    if (q >= 0 && q < 128 * 128) {
        int i = q >> 7, o = q & 127;
        g_Wt2[q] = Wf2[o * 128 + i];
    }
}

// ---------------- degree counts ----------------
__global__ void k_degs(const int* __restrict__ ei) {
    int e = blockIdx.x * blockDim.x + threadIdx.x;
    if (e < NE) {
        atomicAdd(&g_deg[ei[e]], 1);
        atomicAdd(&g_indeg[ei[NE + e]], 1);
    }
}

// ---------------- scan (2 kernels) ----------------
#define SCAN_NB 98
__global__ void k_scan_a() {
    __shared__ int ss[256];
    int b = blockIdx.x, t = threadIdx.x;
    int base = b * 1024 + t * 4;
    int s = 0;
    #pragma unroll
    for (int c = 0; c < 4; c++) { int i = base + c; if (i < NN) s += g_indeg[i]; }
    ss[t] = s; __syncthreads();
    for (int off = 128; off >= 1; off >>= 1) {
        if (t < off) ss[t] += ss[t + off];
        __syncthreads();
    }
    if (t == 0) g_bsum[b] = ss[0];
}
__global__ void k_scan_c() {
    __shared__ int ss[256];
    __shared__ int sbl[SCAN_NB];
    __shared__ int sboff;
    int b = blockIdx.x, t = threadIdx.x;
    if (t < SCAN_NB) sbl[t] = g_bsum[t];
    __syncthreads();
    if (t == 0) {
        int run = 0;
        for (int i = 0; i < b; i++) run += sbl[i];
        sboff = run;
    }
    int base = b * 1024 + t * 4;
    int v[4]; int s = 0;
    #pragma unroll
    for (int c = 0; c < 4; c++) { int i = base + c; v[c] = (i < NN) ? g_indeg[i] : 0; s += v[c]; }
    ss[t] = s; __syncthreads();
    for (int off = 1; off < 256; off <<= 1) {
        int add = (t >= off) ? ss[t - off] : 0;
        __syncthreads();
        ss[t] += add;
        __syncthreads();
    }
    int run = sboff + ss[t] - s;   // exclusive prefix
    #pragma unroll
    for (int c = 0; c < 4; c++) {
        int i = base + c;
        if (i < NN) { g_off[i] = run; g_cur[i] = run; run += v[c]; }
    }
}

// ---------------- fill (fp16 eaz) ----------------
__global__ void k_fill(const int* __restrict__ ei, const float* __restrict__ ea) {
    int e = blockIdx.x * blockDim.x + threadIdx.x;
    if (e >= NE) return;
    int s = ei[e], d = ei[NE + e];
    float nrm = 1.0f / (float)g_deg[s];
    int pos = atomicAdd(&g_cur[d], 1);
    g_src[pos] = s;
    float4 a0 = __ldg((const float4*)(ea + (size_t)e * 8));
    float4 a1 = __ldg((const float4*)(ea + (size_t)e * 8 + 4));
    uint2 u0 = pack4h(a0.x * nrm, a0.y * nrm, a0.z * nrm, a0.w * nrm);
    uint2 u1 = pack4h(a1.x * nrm, a1.y * nrm, a1.z * nrm, a1.w * nrm);
    uint4 u;
    u.x = u0.x; u.y = u0.y; u.z = u1.x; u.w = u1.y;
    *(uint4*)(g_eaz + (size_t)pos * 8) = u;
}

__device__ __forceinline__ void load_eaz8(int pos, float* ef) {
    uint4 u = __ldg((const uint4*)(g_eaz + (size_t)pos * 8));
    float4 lo = unpack4h(make_uint2(u.x, u.y));
    float4 hi = unpack4h(make_uint2(u.z, u.w));
    ef[0] = lo.x; ef[1] = lo.y; ef[2] = lo.z; ef[3] = lo.w;
    ef[4] = hi.x; ef[5] = hi.y; ef[6] = hi.z; ef[7] = hi.w;
}

// ---------------- gather build T1: 4 threads per node (fp16 out) ------------
__global__ __launch_bounds__(256) void k_gath1(const float* __restrict__ x) {
    int tid = blockIdx.x * 256 + threadIdx.x;
    int gn = tid >> 2, j = tid & 3;
    if (gn >= NN) return;
    float acc[32];
    #pragma unroll
    for (int q = 0; q < 32; q++) acc[q] = 0.f;
    int start = g_off[gn], cnt = g_indeg[gn];
    for (int q = 0; q < cnt; q++) {
        int pos = start + q;
        int s = __ldg(g_src + pos);
        float4 xv = __ldg((const float4*)(x + (size_t)s * 16 + j * 4));
        float ef[8];
        load_eaz8(pos, ef);
        #pragma unroll
        for (int f = 0; f < 8; f++) {
            acc[f * 4 + 0] += ef[f] * xv.x;
            acc[f * 4 + 1] += ef[f] * xv.y;
            acc[f * 4 + 2] += ef[f] * xv.z;
            acc[f * 4 + 3] += ef[f] * xv.w;
        }
    }
    __half* dst = g_T1 + (size_t)gn * 128 + j * 4;
    #pragma unroll
    for (int f = 0; f < 8; f++)
        *(uint2*)(dst + f * 16) = pack4h(acc[f * 4], acc[f * 4 + 1],
                                         acc[f * 4 + 2], acc[f * 4 + 3]);
}

// ---------------- gather build T2: 8 threads per node (fp16 in/out) ---------
__global__ __launch_bounds__(256) void k_gath2() {
    int tid = blockIdx.x * 256 + threadIdx.x;
    int gn = tid >> 3, j = tid & 7;
    if (gn >= NN) return;
    float acc[32];
    #pragma unroll
    for (int q = 0; q < 32; q++) acc[q] = 0.f;
    int start = g_off[gn], cnt = g_indeg[gn];
    for (int q = 0; q < cnt; q++) {
        int pos = start + q;
        int s = __ldg(g_src + pos);
        uint2 hraw = __ldg((const uint2*)(g_h1nh + (size_t)s * 32 + j * 4));
        float4 hv = unpack4h(hraw);
        float ef[8];
        load_eaz8(pos, ef);
        #pragma unroll
        for (int f = 0; f < 8; f++) {
            acc[f * 4 + 0] += ef[f] * hv.x;
            acc[f * 4 + 1] += ef[f] * hv.y;
            acc[f * 4 + 2] += ef[f] * hv.z;
            acc[f * 4 + 3] += ef[f] * hv.w;
        }
    }
    __half* dst = g_T2 + (size_t)gn * 256 + j * 4;
    #pragma unroll
    for (int f = 0; f < 8; f++)
        *(uint2*)(dst + f * 32) = pack4h(acc[f * 4], acc[f * 4 + 1],
                                         acc[f * 4 + 2], acc[f * 4 + 3]);
}

// ---------------- GEMM layer1: double-buffered, fp16 T1 loads ---------------
__global__ __launch_bounds__(128) void k_gemm_l1(const float* __restrict__ x,
                                                 const float* __restrict__ Wr1,
                                                 const float* __restrict__ b1) {
    __shared__ float As[2][32 * 132];
    __shared__ float Bs[2][32 * 32];
    __shared__ float s_sum[32], s_sq[32];
    int tid = threadIdx.x;
    if (tid < 32) { s_sum[tid] = 0.f; s_sq[tid] = 0.f; }
    int n0 = blockIdx.x * 128;
    int tn = tid >> 3, to = tid & 7;
    int kq = tid & 7, rr = tid >> 3;

    float acc[8][4];
    #pragma unroll
    for (int m = 0; m < 8; m++)
        #pragma unroll
        for (int c = 0; c < 4; c++) acc[m][c] = 0.f;

    float4 pa[8];
    float  pb[8];

    auto load_stage = [&](int s) {
        #pragma unroll
        for (int it = 0; it < 8; it++) {
            int row = it * 16 + rr;
            int gn = n0 + row;
            float4 v = make_float4(0.f, 0.f, 0.f, 0.f);
            if (gn < NN) {
                if (s < 4) {
                    uint2 raw = __ldg((const uint2*)(g_T1 + (size_t)gn * 128 + s * 32 + kq * 4));
                    v = unpack4h(raw);
                } else if (kq < 4) {
                    v = *(const float4*)(x + (size_t)gn * 16 + kq * 4);
                }
            }
            pa[it] = v;
        }
        #pragma unroll
        for (int i = 0; i < 8; i++) {
            int t = i * 128 + tid;
            float w = 0.f;
            if (s < 4) w = g_W1p[s * 1024 + t];
            else { int k = t >> 5, o = t & 31; if (k < 16) w = Wr1[o * 16 + k]; }
            pb[i] = w;
        }
    };
    auto store_stage = [&](int b) {
        #pragma unroll
        for (int it = 0; it < 8; it++) {
            int row = it * 16 + rr;
            As[b][(kq * 4 + 0) * 132 + row] = pa[it].x;
            As[b][(kq * 4 + 1) * 132 + row] = pa[it].y;
            As[b][(kq * 4 + 2) * 132 + row] = pa[it].z;
            As[b][(kq * 4 + 3) * 132 + row] = pa[it].w;
        }
        #pragma unroll
        for (int i = 0; i < 8; i++) Bs[b][i * 128 + tid] = pb[i];
    };

    load_stage(0);
    store_stage(0);
    __syncthreads();

    for (int s = 0; s < 5; s++) {
        int buf = s & 1;
        if (s < 4) load_stage(s + 1);
        const float* Ab = As[buf];
        const float* Bb = Bs[buf];
        #pragma unroll
        for (int k = 0; k < 32; k++) {
            float4 b = *(const float4*)(Bb + k * 32 + to * 4);
            float4 a0 = *(const float4*)(Ab + k * 132 + tn * 8);
            float4 a1 = *(const float4*)(Ab + k * 132 + tn * 8 + 4);
            const float av[8] = {a0.x, a0.y, a0.z, a0.w, a1.x, a1.y, a1.z, a1.w};
            #pragma unroll
            for (int m = 0; m < 8; m++) {
                acc[m][0] += av[m] * b.x; acc[m][1] += av[m] * b.y;
                acc[m][2] += av[m] * b.z; acc[m][3] += av[m] * b.w;
            }
        }
        if (s < 4) store_stage(buf ^ 1);
        __syncthreads();
    }

    float bv[4];
    #pragma unroll
    for (int c = 0; c < 4; c++) bv[c] = __ldg(b1 + to * 4 + c);
    float ls[4] = {0, 0, 0, 0}, lq[4] = {0, 0, 0, 0};
    #pragma unroll
    for (int m = 0; m < 8; m++) {
        int gn = n0 + tn * 8 + m;
        if (gn < NN) {
            float h0 = acc[m][0] + bv[0], h1 = acc[m][1] + bv[1];
            float h2 = acc[m][2] + bv[2], h3 = acc[m][3] + bv[3];
            *(uint2*)(g_h1h + (size_t)gn * 32 + to * 4) = pack4h(h0, h1, h2, h3);
            ls[0] += h0; ls[1] += h1; ls[2] += h2; ls[3] += h3;
            lq[0] += h0 * h0; lq[1] += h1 * h1; lq[2] += h2 * h2; lq[3] += h3 * h3;
        }
    }
    #pragma unroll
    for (int c = 0; c < 4; c++) {
        atomicAdd(&s_sum[to * 4 + c], ls[c]);
        atomicAdd(&s_sq [to * 4 + c], lq[c]);
    }
    __syncthreads();
    if (tid < 32) {
        atomicAdd(&g_stat1[tid],      s_sum[tid]);
        atomicAdd(&g_stat1[32 + tid], s_sq[tid]);
    }
}

// ---------------- GEMM layer2: double-buffered, fp16 A (R13 tile) -----------
#define L2G_SMEM ((2 * 32 * 132 + 2 * 32 * 64) * 4)
__global__ __launch_bounds__(256) void k_gemm_l2(const float* __restrict__ Wr2,
                                                 const float* __restrict__ b2) {
    extern __shared__ float sml2[];
    float* As0 = sml2;
    float* As1 = As0 + 32 * 132;
    float* Bs0 = As1 + 32 * 132;
    float* Bs1 = Bs0 + 32 * 64;
    __shared__ float s_sum[64], s_sq[64];
    int tid = threadIdx.x;
    if (tid < 64) { s_sum[tid] = 0.f; s_sq[tid] = 0.f; }
    int n0 = blockIdx.x * 128;
    int tn = tid >> 4, to = tid & 15;
    int kq = tid & 7, rr = tid >> 3;

    float acc[8][4];
    #pragma unroll
    for (int m = 0; m < 8; m++)
        #pragma unroll
        for (int c = 0; c < 4; c++) acc[m][c] = 0.f;

    float4 pa[4];
    float  pb[8];

    auto load_stage = [&](int s) {
        #pragma unroll
        for (int it = 0; it < 4; it++) {
            int row = it * 32 + rr;
            int gn = n0 + row;
            float4 v = make_float4(0.f, 0.f, 0.f, 0.f);
            if (gn < NN) {
                const __half* src = (s < 8)
                    ? g_T2 + (size_t)gn * 256 + s * 32 + kq * 4
                    : g_h1nh + (size_t)gn * 32 + kq * 4;
                uint2 raw = __ldg((const uint2*)src);
                v = unpack4h(raw);
            }
            pa[it] = v;
        }
        #pragma unroll
        for (int i = 0; i < 8; i++) {
            int t = i * 256 + tid;
            float w;
            if (s < 8) w = g_W2p[s * 2048 + t];
            else { int k = t >> 6, o = t & 63; w = Wr2[o * 32 + k]; }
            pb[i] = w;
        }
    };
    auto store_stage = [&](float* Ab, float* Bb) {
        #pragma unroll
        for (int it = 0; it < 4; it++) {
            int row = it * 32 + rr;
            Ab[(kq * 4 + 0) * 132 + row] = pa[it].x;
            Ab[(kq * 4 + 1) * 132 + row] = pa[it].y;
            Ab[(kq * 4 + 2) * 132 + row] = pa[it].z;
            Ab[(kq * 4 + 3) * 132 + row] = pa[it].w;
        }
        #pragma unroll
        for (int i = 0; i < 8; i++) Bb[i * 256 + tid] = pb[i];
    };

    load_stage(0);
    store_stage(As0, Bs0);
    __syncthreads();

    for (int s = 0; s < 9; s++) {
        int buf = s & 1;
        if (s < 8) load_stage(s + 1);
        const float* Ab = buf ? As1 : As0;
        const float* Bb = buf ? Bs1 : Bs0;
        #pragma unroll
        for (int k = 0; k < 32; k++) {
            float4 b = *(const float4*)(Bb + k * 64 + to * 4);
            float4 a0 = *(const float4*)(Ab + k * 132 + tn * 8);
            float4 a1 = *(const float4*)(Ab + k * 132 + tn * 8 + 4);
            const float av[8] = {a0.x, a0.y, a0.z, a0.w, a1.x, a1.y, a1.z, a1.w};
            #pragma unroll
            for (int m = 0; m < 8; m++) {
                acc[m][0] += av[m] * b.x; acc[m][1] += av[m] * b.y;
                acc[m][2] += av[m] * b.z; acc[m][3] += av[m] * b.w;
            }
        }
        if (s < 8) store_stage(buf ? As0 : As1, buf ? Bs0 : Bs1);
        __syncthreads();
    }

    float bv[4];
    #pragma unroll
    for (int c = 0; c < 4; c++) bv[c] = __ldg(b2 + to * 4 + c);
    float ls[4] = {0, 0, 0, 0}, lq[4] = {0, 0, 0, 0};
    #pragma unroll
    for (int m = 0; m < 8; m++) {
        int gn = n0 + tn * 8 + m;
        if (gn < NN) {
            float h0 = acc[m][0] + bv[0], h1 = acc[m][1] + bv[1];
            float h2 = acc[m][2] + bv[2], h3 = acc[m][3] + bv[3];
            *(uint2*)(g_h2h + (size_t)gn * 64 + to * 4) = pack4h(h0, h1, h2, h3);
            ls[0] += h0; ls[1] += h1; ls[2] += h2; ls[3] += h3;
            lq[0] += h0 * h0; lq[1] += h1 * h1; lq[2] += h2 * h2; lq[3] += h3 * h3;
        }
    }
    #pragma unroll
    for (int c = 0; c < 4; c++) {
        atomicAdd(&s_sum[to * 4 + c], ls[c]);
        atomicAdd(&s_sq [to * 4 + c], lq[c]);
    }
    __syncthreads();
    if (tid < 64) {
        atomicAdd(&g_stat2[tid],      s_sum[tid]);
        atomicAdd(&g_stat2[64 + tid], s_sq[tid]);
    }
}

// ---------------- BN1 apply + relu -> h1nh (fp16 in/out) ----------------
__global__ void k_bn1(const float* __restrict__ g1, const float* __restrict__ be1) {
    int idx = blockIdx.x * blockDim.x + threadIdx.x;
    if (idx >= NN * 8) return;
    int n = idx >> 3, q = idx & 7;
    const float invN = 1.0f / (float)NN;
    float4 h = unpack4h(__ldg((const uint2*)(g_h1h + (size_t)n * 32 + q * 4)));
    float v[4];
    float* hv = (float*)&h;
    #pragma unroll
    for (int j = 0; j < 4; j++) {
        int c = q * 4 + j;
        float mu = g_stat1[c] * invN;
        float var = g_stat1[32 + c] * invN - mu * mu;
        float rs = rsqrtf(var + EPSV);
        v[j] = fmaxf((hv[j] - mu) * rs * __ldg(g1 + c) + __ldg(be1 + c), 0.f);
    }
    *(uint2*)(g_h1nh + (size_t)n * 32 + q * 4) = pack4h(v[0], v[1], v[2], v[3]);
}

// ---------------- BN2 apply + relu + pooling (4-node runs, fp16 in) ---------
__global__ void k_bn2pool(const float* __restrict__ g2, const float* __restrict__ be2,
                          const int* __restrict__ batch) {
    int idx = blockIdx.x * blockDim.x + threadIdx.x;
    if (idx >= NN * 4) return;
    int nq = idx >> 4, q = idx & 15;
    int n0 = nq * 4;
    const float invN = 1.0f / (float)NN;

    float4 hv[4];
    #pragma unroll
    for (int m = 0; m < 4; m++)
        hv[m] = unpack4h(__ldg((const uint2*)(g_h2h + (size_t)(n0 + m) * 64 + q * 4)));

    float mu[4], rsg[4], ba[4];
    #pragma unroll
    for (int j = 0; j < 4; j++) {
        int c = q * 4 + j;
        float m2 = g_stat2[c] * invN;
        float var = g_stat2[64 + c] * invN - m2 * m2;
        mu[j] = m2;
        rsg[j] = rsqrtf(var + EPSV) * __ldg(g2 + c);
        ba[j] = __ldg(be2 + c);
    }
    float v[4][4];
    #pragma unroll
    for (int m = 0; m < 4; m++) {
        float* hm = (float*)&hv[m];
        #pragma unroll
        for (int j = 0; j < 4; j++)
            v[m][j] = fmaxf((hm[j] - mu[j]) * rsg[j] + ba[j], 0.f);
    }
    int b0 = batch[n0], b3 = batch[n0 + 3];
    if (b0 == b3) {
        red_v4(g_pooled + (size_t)b0 * 64 + q * 4,
               make_float4(v[0][0] + v[1][0] + v[2][0] + v[3][0],
                           v[0][1] + v[1][1] + v[2][1] + v[3][1],
                           v[0][2] + v[1][2] + v[2][2] + v[3][2],
                           v[0][3] + v[1][3] + v[2][3] + v[3][3]));
        if (q == 0) atomicAdd(&g_cnt[b0], 4.0f);
    } else {
        int b1 = batch[n0 + 1], b2i = batch[n0 + 2];
        // pair (0,1)
        if (b0 == b1) {
            red_v4(g_pooled + (size_t)b0 * 64 + q * 4,
                   make_float4(v[0][0] + v[1][0], v[0][1] + v[1][1],
                               v[0][2] + v[1][2], v[0][3] + v[1][3]));
            if (q == 0) atomicAdd(&g_cnt[b0], 2.0f);
        } else {
            red_v4(g_pooled + (size_t)b0 * 64 + q * 4,
                   make_float4(v[0][0], v[0][1], v[0][2], v[0][3]));
            red_v4(g_pooled + (size_t)b1 * 64 + q * 4,
                   make_float4(v[1][0], v[1][1], v[1][2], v[1][3]));
            if (q == 0) { atomicAdd(&g_cnt[b0], 1.0f); atomicAdd(&g_cnt[b1], 1.0f); }
        }
        // pair (2,3)
        if (b2i == b3) {
            red_v4(g_pooled + (size_t)b2i * 64 + q * 4,
                   make_float4(v[2][0] + v[3][0], v[2][1] + v[3][1],
                               v[2][2] + v[3][2], v[2][3] + v[3][3]));
            if (q == 0) atomicAdd(&g_cnt[b2i], 2.0f);
        } else {
            red_v4(g_pooled + (size_t)b2i * 64 + q * 4,
                   make_float4(v[2][0], v[2][1], v[2][2], v[2][3]));
            red_v4(g_pooled + (size_t)b3 * 64 + q * 4,
                   make_float4(v[3][0], v[3][1], v[3][2], v[3][3]));
            if (q == 0) { atomicAdd(&g_cnt[b2i], 1.0f); atomicAdd(&g_cnt[b3], 1.0f); }
        }
    }
}

// ---------------- final MLP ----------------
__global__ __launch_bounds__(128) void k_fc(const float* __restrict__ bf1,
                                            const float* __restrict__ bf2,
                                            float* __restrict__ out) {
    __shared__ float pm[8][64];
    __shared__ float hid[8][128];
    int tid = threadIdx.x;
    int g0 = blockIdx.x * 8;
    for (int t = tid; t < 512; t += 128) {
        int gg = t >> 6, i = t & 63;
        int g = g0 + gg;
        pm[gg][i] = g_pooled[g * 64 + i] / fmaxf(g_cnt[g], 1.0f);
    }
    __syncthreads();

    float acc[8];
    float b = bf1[tid];
    #pragma unroll
    for (int gg = 0; gg < 8; gg++) acc[gg] = b;
    for (int i = 0; i < 64; i++) {
        float w = g_Wt1[i * 128 + tid];
        #pragma unroll
        for (int gg = 0; gg < 8; gg++) acc[gg] += w * pm[gg][i];
    }
    #pragma unroll
    for (int gg = 0; gg < 8; gg++) hid[gg][tid] = fmaxf(acc[gg], 0.f);
    __syncthreads();

    float b2v = bf2[tid];
    #pragma unroll
    for (int gg = 0; gg < 8; gg++) acc[gg] = b2v;
    for (int i = 0; i < 128; i++) {
        float w = g_Wt2[i * 128 + tid];
        #pragma unroll
        for (int gg = 0; gg < 8; gg++) acc[gg] += w * hid[gg][i];
    }
    #pragma unroll
    for (int gg = 0; gg < 8; gg++) {
        int g = g0 + gg;
        if (tid < 64) out[g * 64 + tid] = acc[gg];
        else          out[NG * 64 + g * 64 + (tid - 64)] = acc[gg];
    }
}

// ---------------- launch ----------------
extern "C" void kernel_launch(void* const* d_in, const int* in_sizes, int n_in,
                              void* d_out, int out_size) {
    const float* x    = (const float*)d_in[0];
    const int*   ei   = (const int*)  d_in[1];
    const float* ea   = (const float*)d_in[2];
    const int*   batch= (const int*)  d_in[3];
    const float* We1  = (const float*)d_in[4];
    const float* b1   = (const float*)d_in[5];
    const float* Wr1  = (const float*)d_in[6];
    const float* g1   = (const float*)d_in[7];
    const float* be1  = (const float*)d_in[8];
    const float* We2  = (const float*)d_in[9];
    const float* b2   = (const float*)d_in[10];
    const float* Wr2  = (const float*)d_in[11];
    const float* g2   = (const float*)d_in[12];
    const float* be2  = (const float*)d_in[13];
    const float* Wf1  = (const float*)d_in[14];
    const float* bf1  = (const float*)d_in[15];
    const float* Wf2  = (const float*)d_in[16];
    const float* bf2  = (const float*)d_in[17];
    float* out = (float*)d_out;

    static int attr_set = 0;
    if (!attr_set) {
        cudaFuncSetAttribute(k_gemm_l2, cudaFuncAttributeMaxDynamicSharedMemorySize,
                             L2G_SMEM);
        attr_set = 1;
    }

    k_setup<<<256, 256>>>(We1, We2, Wf1, Wf2);
    k_degs<<<(NE + 255) / 256, 256>>>(ei);
    k_scan_a<<<SCAN_NB, 256>>>();
    k_scan_c<<<SCAN_NB, 256>>>();
    k_fill<<<(NE + 255) / 256, 256>>>(ei, ea);
    k_gath1<<<(NN * 4 + 255) / 256, 256>>>(x);
    k_gemm_l1<<<(NN + 127) / 128, 128>>>(x, Wr1, b1);
    k_bn1<<<(NN * 8 + 255) / 256, 256>>>(g1, be1);
    k_gath2<<<(NN * 8 + 255) / 256, 256>>>();
    k_gemm_l2<<<(NN + 127) / 128, 256, L2G_SMEM>>>(Wr2, b2);
    k_bn2pool<<<(NN * 4 + 255) / 256, 256>>>(g2, be2, batch);
    k_fc<<<NG / 8, 128>>>(bf1, bf2, out);
}

// round 16
// speedup vs baseline: 1.1467x; 1.0855x over previous
#include <cuda_runtime.h>
#include <cuda_fp16.h>

#define NN 100000
#define NE 200000
#define NG 5000
static constexpr float EPSV = 1e-5f;

// ---------------- device scratch ----------------
__device__ __align__(16) __half g_T1[(size_t)NN * 128];   // [n][f*16+i] fp16
__device__ __align__(16) __half g_T2[(size_t)NN * 256];   // [n][f*32+i] fp16
__device__ __align__(16) __half g_h1h[NN * 32];           // fp16 h1 (pre-BN)
__device__ __align__(16) __half g_h1nh[NN * 32];          // fp16 h1n
__device__ __align__(16) __half g_h2h[NN * 64];           // fp16 h2
__device__ __align__(16) float g_pooled[NG * 64];
__device__ float g_cnt[NG];
__device__ int   g_deg[NN];
__device__ int   g_indeg[NN];
__device__ int   g_off[NN];
__device__ int   g_cur[NN];
__device__ int   g_bsum[128];
__device__ int   g_src[NE];
__device__ __align__(16) __half g_eaz[(size_t)NE * 8];    // ea*nrm fp16, dst-sorted
__device__ float g_stat1[64];
__device__ float g_stat2[128];
__device__ __align__(16) float  g_W1p[128 * 32];          // [k=f*16+i][o] fp32
__device__ __align__(16) __half g_W2ph[288 * 64];         // unified layer2 B fp16
__device__ __align__(16) float g_Wt1[64 * 128];
__device__ __align__(16) float g_Wt2[128 * 128];

__device__ __forceinline__ void red_v4(float* p, float4 v) {
    asm volatile("red.global.add.v4.f32 [%0], {%1,%2,%3,%4};"
                 :: "l"(p), "f"(v.x), "f"(v.y), "f"(v.z), "f"(v.w) : "memory");
}

__device__ __forceinline__ uint2 pack4h(float a, float b, float c, float d) {
    __half2 p0 = __floats2half2_rn(a, b);
    __half2 p1 = __floats2half2_rn(c, d);
    uint2 u;
    u.x = *(unsigned*)&p0;
    u.y = *(unsigned*)&p1;
    return u;
}
__device__ __forceinline__ float4 unpack4h(uint2 u) {
    __half2 h0 = *(__half2*)&u.x;
    __half2 h1 = *(__half2*)&u.y;
    float2 f0 = __half22float2(h0);
    float2 f1 = __half22float2(h1);
    return make_float4(f0.x, f0.y, f1.x, f1.y);
}

// ---------------- setup ----------------
__global__ void k_setup(const float* __restrict__ We1, const float* __restrict__ We2,
                        const float* __restrict__ Wr2,
                        const float* __restrict__ Wf1, const float* __restrict__ Wf2) {
    int idx = blockIdx.x * blockDim.x + threadIdx.x;
    int stride = gridDim.x * blockDim.x;
    for (int j = idx; j < NG * 64; j += stride) g_pooled[j] = 0.f;
    for (int j = idx; j < NG;      j += stride) g_cnt[j] = 0.f;
    for (int j = idx; j < NN;      j += stride) { g_deg[j] = 0; g_indeg[j] = 0; }
    if (idx < 64)  g_stat1[idx] = 0.f;
    if (idx < 128) g_stat2[idx] = 0.f;

    if (idx < 128 * 32) {
        int k = idx >> 5, o = idx & 31;
        int f = k >> 4, i = k & 15;
        g_W1p[idx] = We1[((o << 4) + i) * 8 + f];
    }
    int j = idx - 128 * 32;
    if (j >= 0 && j < 288 * 64) {            // unified layer-2 B, fp16
        int k = j >> 6, o = j & 63;
        float w;
        if (k < 256) {
            int f = k >> 5, i = k & 31;
            w = We2[((o << 5) + i) * 8 + f];
        } else {
            w = Wr2[o * 32 + (k - 256)];
        }
        g_W2ph[j] = __float2half(w);
    }
    int p = idx - (128 * 32 + 288 * 64);
    if (p >= 0 && p < 64 * 128) {
        int i = p >> 7, o = p & 127;
        g_Wt1[p] = Wf1[o * 64 + i];
    }
    int q = idx - (128 * 32 + 288 * 64 + 64 * 128);
    if (q >= 0 && q < 128 * 128) {
        int i = q >> 7, o = q & 127;
        g_Wt2[q] = Wf2[o * 128 + i];
    }
}

// ---------------- degree counts ----------------
__global__ void k_degs(const int* __restrict__ ei) {
    int e = blockIdx.x * blockDim.x + threadIdx.x;
    if (e < NE) {
        atomicAdd(&g_deg[ei[e]], 1);
        atomicAdd(&g_indeg[ei[NE + e]], 1);
    }
}

// ---------------- scan (2 kernels) ----------------
#define SCAN_NB 98
__global__ void k_scan_a() {
    __shared__ int ss[256];
    int b = blockIdx.x, t = threadIdx.x;
    int base = b * 1024 + t * 4;
    int s = 0;
    #pragma unroll
    for (int c = 0; c < 4; c++) { int i = base + c; if (i < NN) s += g_indeg[i]; }
    ss[t] = s; __syncthreads();
    for (int off = 128; off >= 1; off >>= 1) {
        if (t < off) ss[t] += ss[t + off];
        __syncthreads();
    }
    if (t == 0) g_bsum[b] = ss[0];
}
__global__ void k_scan_c() {
    __shared__ int ss[256];
    __shared__ int sbl[SCAN_NB];
    __shared__ int sboff;
    int b = blockIdx.x, t = threadIdx.x;
    if (t < SCAN_NB) sbl[t] = g_bsum[t];
    __syncthreads();
    if (t == 0) {
        int run = 0;
        for (int i = 0; i < b; i++) run += sbl[i];
        sboff = run;
    }
    int base = b * 1024 + t * 4;
    int v[4]; int s = 0;
    #pragma unroll
    for (int c = 0; c < 4; c++) { int i = base + c; v[c] = (i < NN) ? g_indeg[i] : 0; s += v[c]; }
    ss[t] = s; __syncthreads();
    for (int off = 1; off < 256; off <<= 1) {
        int add = (t >= off) ? ss[t - off] : 0;
        __syncthreads();
        ss[t] += add;
        __syncthreads();
    }
    int run = sboff + ss[t] - s;
    #pragma unroll
    for (int c = 0; c < 4; c++) {
        int i = base + c;
        if (i < NN) { g_off[i] = run; g_cur[i] = run; run += v[c]; }
    }
}

// ---------------- fill (fp16 eaz) ----------------
__global__ void k_fill(const int* __restrict__ ei, const float* __restrict__ ea) {
    int e = blockIdx.x * blockDim.x + threadIdx.x;
    if (e >= NE) return;
    int s = ei[e], d = ei[NE + e];
    float nrm = 1.0f / (float)g_deg[s];
    int pos = atomicAdd(&g_cur[d], 1);
    g_src[pos] = s;
    float4 a0 = __ldg((const float4*)(ea + (size_t)e * 8));
    float4 a1 = __ldg((const float4*)(ea + (size_t)e * 8 + 4));
    uint2 u0 = pack4h(a0.x * nrm, a0.y * nrm, a0.z * nrm, a0.w * nrm);
    uint2 u1 = pack4h(a1.x * nrm, a1.y * nrm, a1.z * nrm, a1.w * nrm);
    uint4 u;
    u.x = u0.x; u.y = u0.y; u.z = u1.x; u.w = u1.y;
    *(uint4*)(g_eaz + (size_t)pos * 8) = u;
}

__device__ __forceinline__ void load_eaz8(int pos, float* ef) {
    uint4 u = __ldg((const uint4*)(g_eaz + (size_t)pos * 8));
    float4 lo = unpack4h(make_uint2(u.x, u.y));
    float4 hi = unpack4h(make_uint2(u.z, u.w));
    ef[0] = lo.x; ef[1] = lo.y; ef[2] = lo.z; ef[3] = lo.w;
    ef[4] = hi.x; ef[5] = hi.y; ef[6] = hi.z; ef[7] = hi.w;
}

// ---------------- gather build T1: 4 threads per node (fp16 out) ------------
__global__ __launch_bounds__(256) void k_gath1(const float* __restrict__ x) {
    int tid = blockIdx.x * 256 + threadIdx.x;
    int gn = tid >> 2, j = tid & 3;
    if (gn >= NN) return;
    float acc[32];
    #pragma unroll
    for (int q = 0; q < 32; q++) acc[q] = 0.f;
    int start = g_off[gn], cnt = g_indeg[gn];
    for (int q = 0; q < cnt; q++) {
        int pos = start + q;
        int s = __ldg(g_src + pos);
        float4 xv = __ldg((const float4*)(x + (size_t)s * 16 + j * 4));
        float ef[8];
        load_eaz8(pos, ef);
        #pragma unroll
        for (int f = 0; f < 8; f++) {
            acc[f * 4 + 0] += ef[f] * xv.x;
            acc[f * 4 + 1] += ef[f] * xv.y;
            acc[f * 4 + 2] += ef[f] * xv.z;
            acc[f * 4 + 3] += ef[f] * xv.w;
        }
    }
    __half* dst = g_T1 + (size_t)gn * 128 + j * 4;
    #pragma unroll
    for (int f = 0; f < 8; f++)
        *(uint2*)(dst + f * 16) = pack4h(acc[f * 4], acc[f * 4 + 1],
                                         acc[f * 4 + 2], acc[f * 4 + 3]);
}

// ---------------- gather build T2: 8 threads per node (fp16 in/out) ---------
__global__ __launch_bounds__(256) void k_gath2() {
    int tid = blockIdx.x * 256 + threadIdx.x;
    int gn = tid >> 3, j = tid & 7;
    if (gn >= NN) return;
    float acc[32];
    #pragma unroll
    for (int q = 0; q < 32; q++) acc[q] = 0.f;
    int start = g_off[gn], cnt = g_indeg[gn];
    for (int q = 0; q < cnt; q++) {
        int pos = start + q;
        int s = __ldg(g_src + pos);
        uint2 hraw = __ldg((const uint2*)(g_h1nh + (size_t)s * 32 + j * 4));
        float4 hv = unpack4h(hraw);
        float ef[8];
        load_eaz8(pos, ef);
        #pragma unroll
        for (int f = 0; f < 8; f++) {
            acc[f * 4 + 0] += ef[f] * hv.x;
            acc[f * 4 + 1] += ef[f] * hv.y;
            acc[f * 4 + 2] += ef[f] * hv.z;
            acc[f * 4 + 3] += ef[f] * hv.w;
        }
    }
    __half* dst = g_T2 + (size_t)gn * 256 + j * 4;
    #pragma unroll
    for (int f = 0; f < 8; f++)
        *(uint2*)(dst + f * 32) = pack4h(acc[f * 4], acc[f * 4 + 1],
                                         acc[f * 4 + 2], acc[f * 4 + 3]);
}

// ---------------- GEMM layer1: double-buffered, fp16 T1 loads (R13) ---------
__global__ __launch_bounds__(128) void k_gemm_l1(const float* __restrict__ x,
                                                 const float* __restrict__ Wr1,
                                                 const float* __restrict__ b1) {
    __shared__ float As[2][32 * 132];
    __shared__ float Bs[2][32 * 32];
    __shared__ float s_sum[32], s_sq[32];
    int tid = threadIdx.x;
    if (tid < 32) { s_sum[tid] = 0.f; s_sq[tid] = 0.f; }
    int n0 = blockIdx.x * 128;
    int tn = tid >> 3, to = tid & 7;
    int kq = tid & 7, rr = tid >> 3;

    float acc[8][4];
    #pragma unroll
    for (int m = 0; m < 8; m++)
        #pragma unroll
        for (int c = 0; c < 4; c++) acc[m][c] = 0.f;

    float4 pa[8];
    float  pb[8];

    auto load_stage = [&](int s) {
        #pragma unroll
        for (int it = 0; it < 8; it++) {
            int row = it * 16 + rr;
            int gn = n0 + row;
            float4 v = make_float4(0.f, 0.f, 0.f, 0.f);
            if (gn < NN) {
                if (s < 4) {
                    uint2 raw = __ldg((const uint2*)(g_T1 + (size_t)gn * 128 + s * 32 + kq * 4));
                    v = unpack4h(raw);
                } else if (kq < 4) {
                    v = *(const float4*)(x + (size_t)gn * 16 + kq * 4);
                }
            }
            pa[it] = v;
        }
        #pragma unroll
        for (int i = 0; i < 8; i++) {
            int t = i * 128 + tid;
            float w = 0.f;
            if (s < 4) w = g_W1p[s * 1024 + t];
            else { int k = t >> 5, o = t & 31; if (k < 16) w = Wr1[o * 16 + k]; }
            pb[i] = w;
        }
    };
    auto store_stage = [&](int b) {
        #pragma unroll
        for (int it = 0; it < 8; it++) {
            int row = it * 16 + rr;
            As[b][(kq * 4 + 0) * 132 + row] = pa[it].x;
            As[b][(kq * 4 + 1) * 132 + row] = pa[it].y;
            As[b][(kq * 4 + 2) * 132 + row] = pa[it].z;
            As[b][(kq * 4 + 3) * 132 + row] = pa[it].w;
        }
        #pragma unroll
        for (int i = 0; i < 8; i++) Bs[b][i * 128 + tid] = pb[i];
    };

    load_stage(0);
    store_stage(0);
    __syncthreads();

    for (int s = 0; s < 5; s++) {
        int buf = s & 1;
        if (s < 4) load_stage(s + 1);
        const float* Ab = As[buf];
        const float* Bb = Bs[buf];
        #pragma unroll
        for (int k = 0; k < 32; k++) {
            float4 b = *(const float4*)(Bb + k * 32 + to * 4);
            float4 a0 = *(const float4*)(Ab + k * 132 + tn * 8);
            float4 a1 = *(const float4*)(Ab + k * 132 + tn * 8 + 4);
            const float av[8] = {a0.x, a0.y, a0.z, a0.w, a1.x, a1.y, a1.z, a1.w};
            #pragma unroll
            for (int m = 0; m < 8; m++) {
                acc[m][0] += av[m] * b.x; acc[m][1] += av[m] * b.y;
                acc[m][2] += av[m] * b.z; acc[m][3] += av[m] * b.w;
            }
        }
        if (s < 4) store_stage(buf ^ 1);
        __syncthreads();
    }

    float bv[4];
    #pragma unroll
    for (int c = 0; c < 4; c++) bv[c] = __ldg(b1 + to * 4 + c);
    float ls[4] = {0, 0, 0, 0}, lq[4] = {0, 0, 0, 0};
    #pragma unroll
    for (int m = 0; m < 8; m++) {
        int gn = n0 + tn * 8 + m;
        if (gn < NN) {
            float h0 = acc[m][0] + bv[0], h1 = acc[m][1] + bv[1];
            float h2 = acc[m][2] + bv[2], h3 = acc[m][3] + bv[3];
            *(uint2*)(g_h1h + (size_t)gn * 32 + to * 4) = pack4h(h0, h1, h2, h3);
            ls[0] += h0; ls[1] += h1; ls[2] += h2; ls[3] += h3;
            lq[0] += h0 * h0; lq[1] += h1 * h1; lq[2] += h2 * h2; lq[3] += h3 * h3;
        }
    }
    #pragma unroll
    for (int c = 0; c < 4; c++) {
        atomicAdd(&s_sum[to * 4 + c], ls[c]);
        atomicAdd(&s_sq [to * 4 + c], lq[c]);
    }
    __syncthreads();
    if (tid < 32) {
        atomicAdd(&g_stat1[tid],      s_sum[tid]);
        atomicAdd(&g_stat1[32 + tid], s_sq[tid]);
    }
}

// ---------------- GEMM layer2: HFMA2, fp16 A+B in smem ----------------
// 256 thr = 16 tn x 16 to; tile 128n x 64o; thread 8n x 4o (2 half2 accs/row).
// 9 uniform K=32 stages; per-stage half2 accumulate, fp32 flush.
// smem: A [32][136] half x2, B [32][64] half x2 => 25.6 KB.
#define L2G_SMEM (2 * 32 * 136 * 2 + 2 * 32 * 64 * 2)
__global__ __launch_bounds__(256) void k_gemm_l2(const float* __restrict__ b2) {
    extern __shared__ unsigned char sml2raw[];
    unsigned short* As0 = (unsigned short*)sml2raw;          // 32*136 halves
    unsigned short* As1 = As0 + 32 * 136;
    unsigned short* Bs0 = As1 + 32 * 136;                    // 32*64 halves
    unsigned short* Bs1 = Bs0 + 32 * 64;
    __shared__ float s_sum[64], s_sq[64];
    int tid = threadIdx.x;
    if (tid < 64) { s_sum[tid] = 0.f; s_sq[tid] = 0.f; }
    int n0 = blockIdx.x * 128;
    int tn = tid >> 4, to = tid & 15;
    int kq = tid & 7, rr = tid >> 3;

    float acc[8][4];
    #pragma unroll
    for (int m = 0; m < 8; m++)
        #pragma unroll
        for (int c = 0; c < 4; c++) acc[m][c] = 0.f;

    uint2 pa[4];
    uint4 pb;

    auto load_stage = [&](int s) {
        #pragma unroll
        for (int it = 0; it < 4; it++) {
            int row = it * 32 + rr;
            int gn = n0 + row;
            uint2 raw = make_uint2(0u, 0u);
            if (gn < NN) {
                const __half* src = (s < 8)
                    ? g_T2 + (size_t)gn * 256 + s * 32 + kq * 4
                    : g_h1nh + (size_t)gn * 32 + kq * 4;
                raw = __ldg((const uint2*)src);
            }
            pa[it] = raw;
        }
        pb = __ldg((const uint4*)(g_W2ph + s * 2048) + tid);
    };
    auto store_stage = [&](unsigned short* Ab, unsigned short* Bb) {
        #pragma unroll
        for (int it = 0; it < 4; it++) {
            int row = it * 32 + rr;
            unsigned lo = pa[it].x, hi = pa[it].y;
            Ab[(kq * 4 + 0) * 136 + row] = (unsigned short)(lo & 0xffff);
            Ab[(kq * 4 + 1) * 136 + row] = (unsigned short)(lo >> 16);
            Ab[(kq * 4 + 2) * 136 + row] = (unsigned short)(hi & 0xffff);
            Ab[(kq * 4 + 3) * 136 + row] = (unsigned short)(hi >> 16);
        }
        *((uint4*)Bb + tid) = pb;
    };

    load_stage(0);
    store_stage(As0, Bs0);
    __syncthreads();

    for (int s = 0; s < 9; s++) {
        int buf = s & 1;
        if (s < 8) load_stage(s + 1);
        const unsigned short* Ab = buf ? As1 : As0;
        const unsigned short* Bb = buf ? Bs1 : Bs0;

        __half2 acc2[8][2];
        #pragma unroll
        for (int m = 0; m < 8; m++) {
            acc2[m][0] = __float2half2_rn(0.f);
            acc2[m][1] = __float2half2_rn(0.f);
        }
        #pragma unroll
        for (int k = 0; k < 32; k++) {
            uint4 a8 = *(const uint4*)(Ab + k * 136 + tn * 8);
            uint2 b4 = *(const uint2*)(Bb + k * 64 + to * 4);
            __half2 b01 = *(__half2*)&b4.x;
            __half2 b23 = *(__half2*)&b4.y;
            __half2 h01 = *(__half2*)&a8.x;
            __half2 h23 = *(__half2*)&a8.y;
            __half2 h45 = *(__half2*)&a8.z;
            __half2 h67 = *(__half2*)&a8.w;
            __half2 am;
            am = __low2half2(h01);
            acc2[0][0] = __hfma2(am, b01, acc2[0][0]);
            acc2[0][1] = __hfma2(am, b23, acc2[0][1]);
            am = __high2half2(h01);
            acc2[1][0] = __hfma2(am, b01, acc2[1][0]);
            acc2[1][1] = __hfma2(am, b23, acc2[1][1]);
            am = __low2half2(h23);
            acc2[2][0] = __hfma2(am, b01, acc2[2][0]);
            acc2[2][1] = __hfma2(am, b23, acc2[2][1]);
            am = __high2half2(h23);
            acc2[3][0] = __hfma2(am, b01, acc2[3][0]);
            acc2[3][1] = __hfma2(am, b23, acc2[3][1]);
            am = __low2half2(h45);
            acc2[4][0] = __hfma2(am, b01, acc2[4][0]);
            acc2[4][1] = __hfma2(am, b23, acc2[4][1]);
            am = __high2half2(h45);
            acc2[5][0] = __hfma2(am, b01, acc2[5][0]);
            acc2[5][1] = __hfma2(am, b23, acc2[5][1]);
            am = __low2half2(h67);
            acc2[6][0] = __hfma2(am, b01, acc2[6][0]);
            acc2[6][1] = __hfma2(am, b23, acc2[6][1]);
            am = __high2half2(h67);
            acc2[7][0] = __hfma2(am, b01, acc2[7][0]);
            acc2[7][1] = __hfma2(am, b23, acc2[7][1]);
        }
        // flush to fp32
        #pragma unroll
        for (int m = 0; m < 8; m++) {
            float2 f0 = __half22float2(acc2[m][0]);
            float2 f1 = __half22float2(acc2[m][1]);
            acc[m][0] += f0.x; acc[m][1] += f0.y;
            acc[m][2] += f1.x; acc[m][3] += f1.y;
        }
        if (s < 8) store_stage(buf ? As0 : As1, buf ? Bs0 : Bs1);
        __syncthreads();
    }

    float bv[4];
    #pragma unroll
    for (int c = 0; c < 4; c++) bv[c] = __ldg(b2 + to * 4 + c);
    float ls[4] = {0, 0, 0, 0}, lq[4] = {0, 0, 0, 0};
    #pragma unroll
    for (int m = 0; m < 8; m++) {
        int gn = n0 + tn * 8 + m;
        if (gn < NN) {
            float h0 = acc[m][0] + bv[0], h1 = acc[m][1] + bv[1];
            float h2 = acc[m][2] + bv[2], h3 = acc[m][3] + bv[3];
            *(uint2*)(g_h2h + (size_t)gn * 64 + to * 4) = pack4h(h0, h1, h2, h3);
            ls[0] += h0; ls[1] += h1; ls[2] += h2; ls[3] += h3;
            lq[0] += h0 * h0; lq[1] += h1 * h1; lq[2] += h2 * h2; lq[3] += h3 * h3;
        }
    }
    #pragma unroll
    for (int c = 0; c < 4; c++) {
        atomicAdd(&s_sum[to * 4 + c], ls[c]);
        atomicAdd(&s_sq [to * 4 + c], lq[c]);
    }
    __syncthreads();
    if (tid < 64) {
        atomicAdd(&g_stat2[tid],      s_sum[tid]);
        atomicAdd(&g_stat2[64 + tid], s_sq[tid]);
    }
}

// ---------------- BN1 apply + relu -> h1nh (fp16 in/out) ----------------
__global__ void k_bn1(const float* __restrict__ g1, const float* __restrict__ be1) {
    int idx = blockIdx.x * blockDim.x + threadIdx.x;
    if (idx >= NN * 8) return;
    int n = idx >> 3, q = idx & 7;
    const float invN = 1.0f / (float)NN;
    float4 h = unpack4h(__ldg((const uint2*)(g_h1h + (size_t)n * 32 + q * 4)));
    float v[4];
    float* hv = (float*)&h;
    #pragma unroll
    for (int j = 0; j < 4; j++) {
        int c = q * 4 + j;
        float mu = g_stat1[c] * invN;
        float var = g_stat1[32 + c] * invN - mu * mu;
        float rs = rsqrtf(var + EPSV);
        v[j] = fmaxf((hv[j] - mu) * rs * __ldg(g1 + c) + __ldg(be1 + c), 0.f);
    }
    *(uint2*)(g_h1nh + (size_t)n * 32 + q * 4) = pack4h(v[0], v[1], v[2], v[3]);
}

// ---------------- BN2 apply + relu + pooling (4-node runs, fp16 in) ---------
__global__ void k_bn2pool(const float* __restrict__ g2, const float* __restrict__ be2,
                          const int* __restrict__ batch) {
    int idx = blockIdx.x * blockDim.x + threadIdx.x;
    if (idx >= NN * 4) return;
    int nq = idx >> 4, q = idx & 15;
    int n0 = nq * 4;
    const float invN = 1.0f / (float)NN;

    float4 hv[4];
    #pragma unroll
    for (int m = 0; m < 4; m++)
        hv[m] = unpack4h(__ldg((const uint2*)(g_h2h + (size_t)(n0 + m) * 64 + q * 4)));

    float mu[4], rsg[4], ba[4];
    #pragma unroll
    for (int j = 0; j < 4; j++) {
        int c = q * 4 + j;
        float m2 = g_stat2[c] * invN;
        float var = g_stat2[64 + c] * invN - m2 * m2;
        mu[j] = m2;
        rsg[j] = rsqrtf(var + EPSV) * __ldg(g2 + c);
        ba[j] = __ldg(be2 + c);
    }
    float v[4][4];
    #pragma unroll
    for (int m = 0; m < 4; m++) {
        float* hm = (float*)&hv[m];
        #pragma unroll
        for (int j = 0; j < 4; j++)
            v[m][j] = fmaxf((hm[j] - mu[j]) * rsg[j] + ba[j], 0.f);
    }
    int b0 = batch[n0], b3 = batch[n0 + 3];
    if (b0 == b3) {
        red_v4(g_pooled + (size_t)b0 * 64 + q * 4,
               make_float4(v[0][0] + v[1][0] + v[2][0] + v[3][0],
                           v[0][1] + v[1][1] + v[2][1] + v[3][1],
                           v[0][2] + v[1][2] + v[2][2] + v[3][2],
                           v[0][3] + v[1][3] + v[2][3] + v[3][3]));
        if (q == 0) atomicAdd(&g_cnt[b0], 4.0f);
    } else {
        int b1 = batch[n0 + 1], b2i = batch[n0 + 2];
        if (b0 == b1) {
            red_v4(g_pooled + (size_t)b0 * 64 + q * 4,
                   make_float4(v[0][0] + v[1][0], v[0][1] + v[1][1],
                               v[0][2] + v[1][2], v[0][3] + v[1][3]));
            if (q == 0) atomicAdd(&g_cnt[b0], 2.0f);
        } else {
            red_v4(g_pooled + (size_t)b0 * 64 + q * 4,
                   make_float4(v[0][0], v[0][1], v[0][2], v[0][3]));
            red_v4(g_pooled + (size_t)b1 * 64 + q * 4,
                   make_float4(v[1][0], v[1][1], v[1][2], v[1][3]));
            if (q == 0) { atomicAdd(&g_cnt[b0], 1.0f); atomicAdd(&g_cnt[b1], 1.0f); }
        }
        if (b2i == b3) {
            red_v4(g_pooled + (size_t)b2i * 64 + q * 4,
                   make_float4(v[2][0] + v[3][0], v[2][1] + v[3][1],
                               v[2][2] + v[3][2], v[2][3] + v[3][3]));
            if (q == 0) atomicAdd(&g_cnt[b2i], 2.0f);
        } else {
            red_v4(g_pooled + (size_t)b2i * 64 + q * 4,
                   make_float4(v[2][0], v[2][1], v[2][2], v[2][3]));
            red_v4(g_pooled + (size_t)b3 * 64 + q * 4,
                   make_float4(v[3][0], v[3][1], v[3][2], v[3][3]));
            if (q == 0) { atomicAdd(&g_cnt[b2i], 1.0f); atomicAdd(&g_cnt[b3], 1.0f); }
        }
    }
}

// ---------------- final MLP ----------------
__global__ __launch_bounds__(128) void k_fc(const float* __restrict__ bf1,
                                            const float* __restrict__ bf2,
                                            float* __restrict__ out) {
    __shared__ float pm[8][64];
    __shared__ float hid[8][128];
    int tid = threadIdx.x;
    int g0 = blockIdx.x * 8;
    for (int t = tid; t < 512; t += 128) {
        int gg = t >> 6, i = t & 63;
        int g = g0 + gg;
        pm[gg][i] = g_pooled[g * 64 + i] / fmaxf(g_cnt[g], 1.0f);
    }
    __syncthreads();

    float acc[8];
    float b = bf1[tid];
    #pragma unroll
    for (int gg = 0; gg < 8; gg++) acc[gg] = b;
    for (int i = 0; i < 64; i++) {
        float w = g_Wt1[i * 128 + tid];
        #pragma unroll
        for (int gg = 0; gg < 8; gg++) acc[gg] += w * pm[gg][i];
    }
    #pragma unroll
    for (int gg = 0; gg < 8; gg++) hid[gg][tid] = fmaxf(acc[gg], 0.f);
    __syncthreads();

    float b2v = bf2[tid];
    #pragma unroll
    for (int gg = 0; gg < 8; gg++) acc[gg] = b2v;
    for (int i = 0; i < 128; i++) {
        float w = g_Wt2[i * 128 + tid];
        #pragma unroll
        for (int gg = 0; gg < 8; gg++) acc[gg] += w * hid[gg][i];
    }
    #pragma unroll
    for (int gg = 0; gg < 8; gg++) {
        int g = g0 + gg;
        if (tid < 64) out[g * 64 + tid] = acc[gg];
        else          out[NG * 64 + g * 64 + (tid - 64)] = acc[gg];
    }
}

// ---------------- launch ----------------
extern "C" void kernel_launch(void* const* d_in, const int* in_sizes, int n_in,
                              void* d_out, int out_size) {
    const float* x    = (const float*)d_in[0];
    const int*   ei   = (const int*)  d_in[1];
    const float* ea   = (const float*)d_in[2];
    const int*   batch= (const int*)  d_in[3];
    const float* We1  = (const float*)d_in[4];
    const float* b1   = (const float*)d_in[5];
    const float* Wr1  = (const float*)d_in[6];
    const float* g1   = (const float*)d_in[7];
    const float* be1  = (const float*)d_in[8];
    const float* We2  = (const float*)d_in[9];
    const float* b2   = (const float*)d_in[10];
    const float* Wr2  = (const float*)d_in[11];
    const float* g2   = (const float*)d_in[12];
    const float* be2  = (const float*)d_in[13];
    const float* Wf1  = (const float*)d_in[14];
    const float* bf1  = (const float*)d_in[15];
    const float* Wf2  = (const float*)d_in[16];
    const float* bf2  = (const float*)d_in[17];
    float* out = (float*)d_out;

    static int attr_set = 0;
    if (!attr_set) {
        cudaFuncSetAttribute(k_gemm_l2, cudaFuncAttributeMaxDynamicSharedMemorySize,
                             L2G_SMEM);
        attr_set = 1;
    }

    k_setup<<<256, 256>>>(We1, We2, Wr2, Wf1, Wf2);
    k_degs<<<(NE + 255) / 256, 256>>>(ei);
    k_scan_a<<<SCAN_NB, 256>>>();
    k_scan_c<<<SCAN_NB, 256>>>();
    k_fill<<<(NE + 255) / 256, 256>>>(ei, ea);
    k_gath1<<<(NN * 4 + 255) / 256, 256>>>(x);
    k_gemm_l1<<<(NN + 127) / 128, 128>>>(x, Wr1, b1);
    k_bn1<<<(NN * 8 + 255) / 256, 256>>>(g1, be1);
    k_gath2<<<(NN * 8 + 255) / 256, 256>>>();
    k_gemm_l2<<<(NN + 127) / 128, 256, L2G_SMEM>>>(b2);
    k_bn2pool<<<(NN * 4 + 255) / 256, 256>>>(g2, be2, batch);
    k_fc<<<NG / 8, 128>>>(bf1, bf2, out);
}

// round 17
// speedup vs baseline: 1.2204x; 1.0643x over previous
#include <cuda_runtime.h>
#include <cuda_fp16.h>

#define NN 100000
#define NE 200000
#define NG 5000
static constexpr float EPSV = 1e-5f;

// ---------------- device scratch ----------------
__device__ __align__(16) __half g_T1[(size_t)NN * 128];   // [n][f*16+i] fp16
__device__ __align__(16) __half g_T2[(size_t)NN * 256];   // [n][f*32+i] fp16
__device__ __align__(16) __half g_h1h[NN * 32];           // fp16 h1 (pre-BN)
__device__ __align__(16) __half g_h1nh[NN * 32];          // fp16 h1n
__device__ __align__(16) __half g_h2h[NN * 64];           // fp16 h2
__device__ __align__(16) float g_pooled[NG * 64];
__device__ float g_cnt[NG];
__device__ int   g_deg[NN];
__device__ int   g_indeg[NN];
__device__ int   g_off[NN];
__device__ int   g_cur[NN];
__device__ int   g_bsum[128];
__device__ int   g_src[NE];
__device__ __align__(16) __half g_eaz[(size_t)NE * 8];    // ea*nrm fp16, dst-sorted
__device__ float g_stat1[64];
__device__ float g_stat2[128];
__device__ __align__(16) __half g_W1ph[160 * 32];         // unified layer1 B fp16 (K padded)
__device__ __align__(16) __half g_W2ph[288 * 64];         // unified layer2 B fp16
__device__ __align__(16) float g_Wt1[64 * 128];
__device__ __align__(16) float g_Wt2[128 * 128];

__device__ __forceinline__ void red_v4(float* p, float4 v) {
    asm volatile("red.global.add.v4.f32 [%0], {%1,%2,%3,%4};"
                 :: "l"(p), "f"(v.x), "f"(v.y), "f"(v.z), "f"(v.w) : "memory");
}

__device__ __forceinline__ uint2 pack4h(float a, float b, float c, float d) {
    __half2 p0 = __floats2half2_rn(a, b);
    __half2 p1 = __floats2half2_rn(c, d);
    uint2 u;
    u.x = *(unsigned*)&p0;
    u.y = *(unsigned*)&p1;
    return u;
}
__device__ __forceinline__ float4 unpack4h(uint2 u) {
    __half2 h0 = *(__half2*)&u.x;
    __half2 h1 = *(__half2*)&u.y;
    float2 f0 = __half22float2(h0);
    float2 f1 = __half22float2(h1);
    return make_float4(f0.x, f0.y, f1.x, f1.y);
}

// ---------------- setup ----------------
__global__ void k_setup(const float* __restrict__ We1, const float* __restrict__ Wr1,
                        const float* __restrict__ We2, const float* __restrict__ Wr2,
                        const float* __restrict__ Wf1, const float* __restrict__ Wf2) {
    int idx = blockIdx.x * blockDim.x + threadIdx.x;
    int stride = gridDim.x * blockDim.x;
    for (int j = idx; j < NG * 64; j += stride) g_pooled[j] = 0.f;
    for (int j = idx; j < NG;      j += stride) g_cnt[j] = 0.f;
    for (int j = idx; j < NN;      j += stride) { g_deg[j] = 0; g_indeg[j] = 0; }
    if (idx < 64)  g_stat1[idx] = 0.f;
    if (idx < 128) g_stat2[idx] = 0.f;

    if (idx < 160 * 32) {                    // unified layer-1 B, fp16, K padded to 160
        int k = idx >> 5, o = idx & 31;
        float w = 0.f;
        if (k < 128) {
            int f = k >> 4, i = k & 15;
            w = We1[((o << 4) + i) * 8 + f];
        } else if (k < 144) {
            w = Wr1[o * 16 + (k - 128)];
        }
        g_W1ph[idx] = __float2half(w);
    }
    int j = idx - 160 * 32;
    if (j >= 0 && j < 288 * 64) {            // unified layer-2 B, fp16
        int k = j >> 6, o = j & 63;
        float w;
        if (k < 256) {
            int f = k >> 5, i = k & 31;
            w = We2[((o << 5) + i) * 8 + f];
        } else {
            w = Wr2[o * 32 + (k - 256)];
        }
        g_W2ph[j] = __float2half(w);
    }
    int p = idx - (160 * 32 + 288 * 64);
    if (p >= 0 && p < 64 * 128) {
        int i = p >> 7, o = p & 127;
        g_Wt1[p] = Wf1[o * 64 + i];
    }
    int q = idx - (160 * 32 + 288 * 64 + 64 * 128);
    if (q >= 0 && q < 128 * 128) {
        int i = q >> 7, o = q & 127;
        g_Wt2[q] = Wf2[o * 128 + i];
    }
}

// ---------------- degree counts ----------------
__global__ void k_degs(const int* __restrict__ ei) {
    int e = blockIdx.x * blockDim.x + threadIdx.x;
    if (e < NE) {
        atomicAdd(&g_deg[ei[e]], 1);
        atomicAdd(&g_indeg[ei[NE + e]], 1);
    }
}

// ---------------- scan (2 kernels) ----------------
#define SCAN_NB 98
__global__ void k_scan_a() {
    __shared__ int ss[256];
    int b = blockIdx.x, t = threadIdx.x;
    int base = b * 1024 + t * 4;
    int s = 0;
    #pragma unroll
    for (int c = 0; c < 4; c++) { int i = base + c; if (i < NN) s += g_indeg[i]; }
    ss[t] = s; __syncthreads();
    for (int off = 128; off >= 1; off >>= 1) {
        if (t < off) ss[t] += ss[t + off];
        __syncthreads();
    }
    if (t == 0) g_bsum[b] = ss[0];
}
__global__ void k_scan_c() {
    __shared__ int ss[256];
    __shared__ int sbl[SCAN_NB];
    __shared__ int sboff;
    int b = blockIdx.x, t = threadIdx.x;
    if (t < SCAN_NB) sbl[t] = g_bsum[t];
    __syncthreads();
    if (t == 0) {
        int run = 0;
        for (int i = 0; i < b; i++) run += sbl[i];
        sboff = run;
    }
    int base = b * 1024 + t * 4;
    int v[4]; int s = 0;
    #pragma unroll
    for (int c = 0; c < 4; c++) { int i = base + c; v[c] = (i < NN) ? g_indeg[i] : 0; s += v[c]; }
    ss[t] = s; __syncthreads();
    for (int off = 1; off < 256; off <<= 1) {
        int add = (t >= off) ? ss[t - off] : 0;
        __syncthreads();
        ss[t] += add;
        __syncthreads();
    }
    int run = sboff + ss[t] - s;
    #pragma unroll
    for (int c = 0; c < 4; c++) {
        int i = base + c;
        if (i < NN) { g_off[i] = run; g_cur[i] = run; run += v[c]; }
    }
}

// ---------------- fill (fp16 eaz) ----------------
__global__ void k_fill(const int* __restrict__ ei, const float* __restrict__ ea) {
    int e = blockIdx.x * blockDim.x + threadIdx.x;
    if (e >= NE) return;
    int s = ei[e], d = ei[NE + e];
    float nrm = 1.0f / (float)g_deg[s];
    int pos = atomicAdd(&g_cur[d], 1);
    g_src[pos] = s;
    float4 a0 = __ldg((const float4*)(ea + (size_t)e * 8));
    float4 a1 = __ldg((const float4*)(ea + (size_t)e * 8 + 4));
    uint2 u0 = pack4h(a0.x * nrm, a0.y * nrm, a0.z * nrm, a0.w * nrm);
    uint2 u1 = pack4h(a1.x * nrm, a1.y * nrm, a1.z * nrm, a1.w * nrm);
    uint4 u;
    u.x = u0.x; u.y = u0.y; u.z = u1.x; u.w = u1.y;
    *(uint4*)(g_eaz + (size_t)pos * 8) = u;
}

__device__ __forceinline__ void load_eaz8(int pos, float* ef) {
    uint4 u = __ldg((const uint4*)(g_eaz + (size_t)pos * 8));
    float4 lo = unpack4h(make_uint2(u.x, u.y));
    float4 hi = unpack4h(make_uint2(u.z, u.w));
    ef[0] = lo.x; ef[1] = lo.y; ef[2] = lo.z; ef[3] = lo.w;
    ef[4] = hi.x; ef[5] = hi.y; ef[6] = hi.z; ef[7] = hi.w;
}

// ---------------- gather build T1: 4 threads per node (fp16 out) ------------
__global__ __launch_bounds__(256) void k_gath1(const float* __restrict__ x) {
    int tid = blockIdx.x * 256 + threadIdx.x;
    int gn = tid >> 2, j = tid & 3;
    if (gn >= NN) return;
    float acc[32];
    #pragma unroll
    for (int q = 0; q < 32; q++) acc[q] = 0.f;
    int start = g_off[gn], cnt = g_indeg[gn];
    for (int q = 0; q < cnt; q++) {
        int pos = start + q;
        int s = __ldg(g_src + pos);
        float4 xv = __ldg((const float4*)(x + (size_t)s * 16 + j * 4));
        float ef[8];
        load_eaz8(pos, ef);
        #pragma unroll
        for (int f = 0; f < 8; f++) {
            acc[f * 4 + 0] += ef[f] * xv.x;
            acc[f * 4 + 1] += ef[f] * xv.y;
            acc[f * 4 + 2] += ef[f] * xv.z;
            acc[f * 4 + 3] += ef[f] * xv.w;
        }
    }
    __half* dst = g_T1 + (size_t)gn * 128 + j * 4;
    #pragma unroll
    for (int f = 0; f < 8; f++)
        *(uint2*)(dst + f * 16) = pack4h(acc[f * 4], acc[f * 4 + 1],
                                         acc[f * 4 + 2], acc[f * 4 + 3]);
}

// ---------------- gather build T2: 8 threads per node (fp16 in/out) ---------
__global__ __launch_bounds__(256) void k_gath2() {
    int tid = blockIdx.x * 256 + threadIdx.x;
    int gn = tid >> 3, j = tid & 7;
    if (gn >= NN) return;
    float acc[32];
    #pragma unroll
    for (int q = 0; q < 32; q++) acc[q] = 0.f;
    int start = g_off[gn], cnt = g_indeg[gn];
    for (int q = 0; q < cnt; q++) {
        int pos = start + q;
        int s = __ldg(g_src + pos);
        uint2 hraw = __ldg((const uint2*)(g_h1nh + (size_t)s * 32 + j * 4));
        float4 hv = unpack4h(hraw);
        float ef[8];
        load_eaz8(pos, ef);
        #pragma unroll
        for (int f = 0; f < 8; f++) {
            acc[f * 4 + 0] += ef[f] * hv.x;
            acc[f * 4 + 1] += ef[f] * hv.y;
            acc[f * 4 + 2] += ef[f] * hv.z;
            acc[f * 4 + 3] += ef[f] * hv.w;
        }
    }
    __half* dst = g_T2 + (size_t)gn * 256 + j * 4;
    #pragma unroll
    for (int f = 0; f < 8; f++)
        *(uint2*)(dst + f * 32) = pack4h(acc[f * 4], acc[f * 4 + 1],
                                         acc[f * 4 + 2], acc[f * 4 + 3]);
}

// ---------------- GEMM layer1: HFMA2, fp16 A+B, 5 uniform K=32 stages -------
// 128 thr = 16 tn x 8 to; tile 128n x 32o; thread 8n x 4o.
__global__ __launch_bounds__(128) void k_gemm_l1(const float* __restrict__ x,
                                                 const float* __restrict__ b1) {
    __shared__ unsigned short As[2][32 * 136];
    __shared__ unsigned short Bs[2][32 * 32];
    __shared__ float s_sum[32], s_sq[32];
    int tid = threadIdx.x;
    if (tid < 32) { s_sum[tid] = 0.f; s_sq[tid] = 0.f; }
    int n0 = blockIdx.x * 128;
    int tn = tid >> 3, to = tid & 7;
    int kq = tid & 7, rr = tid >> 3;

    float acc[8][4];
    #pragma unroll
    for (int m = 0; m < 8; m++)
        #pragma unroll
        for (int c = 0; c < 4; c++) acc[m][c] = 0.f;

    uint2 pa[8];
    uint4 pb;

    auto load_stage = [&](int s) {
        #pragma unroll
        for (int it = 0; it < 8; it++) {
            int row = it * 16 + rr;
            int gn = n0 + row;
            uint2 raw = make_uint2(0u, 0u);
            if (gn < NN) {
                if (s < 4) {
                    raw = __ldg((const uint2*)(g_T1 + (size_t)gn * 128 + s * 32 + kq * 4));
                } else if (kq < 4) {
                    float4 v = *(const float4*)(x + (size_t)gn * 16 + kq * 4);
                    raw = pack4h(v.x, v.y, v.z, v.w);
                }
            }
            pa[it] = raw;
        }
        pb = __ldg((const uint4*)(g_W1ph + s * 1024) + tid);
    };
    auto store_stage = [&](int b) {
        #pragma unroll
        for (int it = 0; it < 8; it++) {
            int row = it * 16 + rr;
            unsigned lo = pa[it].x, hi = pa[it].y;
            As[b][(kq * 4 + 0) * 136 + row] = (unsigned short)(lo & 0xffff);
            As[b][(kq * 4 + 1) * 136 + row] = (unsigned short)(lo >> 16);
            As[b][(kq * 4 + 2) * 136 + row] = (unsigned short)(hi & 0xffff);
            As[b][(kq * 4 + 3) * 136 + row] = (unsigned short)(hi >> 16);
        }
        *((uint4*)Bs[b] + tid) = pb;
    };

    load_stage(0);
    store_stage(0);
    __syncthreads();

    for (int s = 0; s < 5; s++) {
        int buf = s & 1;
        if (s < 4) load_stage(s + 1);
        const unsigned short* Ab = As[buf];
        const unsigned short* Bb = Bs[buf];

        __half2 acc2[8][2];
        #pragma unroll
        for (int m = 0; m < 8; m++) {
            acc2[m][0] = __float2half2_rn(0.f);
            acc2[m][1] = __float2half2_rn(0.f);
        }
        #pragma unroll
        for (int k = 0; k < 32; k++) {
            uint4 a8 = *(const uint4*)(Ab + k * 136 + tn * 8);
            uint2 b4 = *(const uint2*)(Bb + k * 32 + to * 4);
            __half2 b01 = *(__half2*)&b4.x;
            __half2 b23 = *(__half2*)&b4.y;
            __half2 h01 = *(__half2*)&a8.x;
            __half2 h23 = *(__half2*)&a8.y;
            __half2 h45 = *(__half2*)&a8.z;
            __half2 h67 = *(__half2*)&a8.w;
            __half2 am;
            am = __low2half2(h01);
            acc2[0][0] = __hfma2(am, b01, acc2[0][0]);
            acc2[0][1] = __hfma2(am, b23, acc2[0][1]);
            am = __high2half2(h01);
            acc2[1][0] = __hfma2(am, b01, acc2[1][0]);
            acc2[1][1] = __hfma2(am, b23, acc2[1][1]);
            am = __low2half2(h23);
            acc2[2][0] = __hfma2(am, b01, acc2[2][0]);
            acc2[2][1] = __hfma2(am, b23, acc2[2][1]);
            am = __high2half2(h23);
            acc2[3][0] = __hfma2(am, b01, acc2[3][0]);
            acc2[3][1] = __hfma2(am, b23, acc2[3][1]);
            am = __low2half2(h45);
            acc2[4][0] = __hfma2(am, b01, acc2[4][0]);
            acc2[4][1] = __hfma2(am, b23, acc2[4][1]);
            am = __high2half2(h45);
            acc2[5][0] = __hfma2(am, b01, acc2[5][0]);
            acc2[5][1] = __hfma2(am, b23, acc2[5][1]);
            am = __low2half2(h67);
            acc2[6][0] = __hfma2(am, b01, acc2[6][0]);
            acc2[6][1] = __hfma2(am, b23, acc2[6][1]);
            am = __high2half2(h67);
            acc2[7][0] = __hfma2(am, b01, acc2[7][0]);
            acc2[7][1] = __hfma2(am, b23, acc2[7][1]);
        }
        #pragma unroll
        for (int m = 0; m < 8; m++) {
            float2 f0 = __half22float2(acc2[m][0]);
            float2 f1 = __half22float2(acc2[m][1]);
            acc[m][0] += f0.x; acc[m][1] += f0.y;
            acc[m][2] += f1.x; acc[m][3] += f1.y;
        }
        if (s < 4) store_stage(buf ^ 1);
        __syncthreads();
    }

    float bv[4];
    #pragma unroll
    for (int c = 0; c < 4; c++) bv[c] = __ldg(b1 + to * 4 + c);
    float ls[4] = {0, 0, 0, 0}, lq[4] = {0, 0, 0, 0};
    #pragma unroll
    for (int m = 0; m < 8; m++) {
        int gn = n0 + tn * 8 + m;
        if (gn < NN) {
            float h0 = acc[m][0] + bv[0], h1 = acc[m][1] + bv[1];
            float h2 = acc[m][2] + bv[2], h3 = acc[m][3] + bv[3];
            *(uint2*)(g_h1h + (size_t)gn * 32 + to * 4) = pack4h(h0, h1, h2, h3);
            ls[0] += h0; ls[1] += h1; ls[2] += h2; ls[3] += h3;
            lq[0] += h0 * h0; lq[1] += h1 * h1; lq[2] += h2 * h2; lq[3] += h3 * h3;
        }
    }
    #pragma unroll
    for (int c = 0; c < 4; c++) {
        atomicAdd(&s_sum[to * 4 + c], ls[c]);
        atomicAdd(&s_sq [to * 4 + c], lq[c]);
    }
    __syncthreads();
    if (tid < 32) {
        atomicAdd(&g_stat1[tid],      s_sum[tid]);
        atomicAdd(&g_stat1[32 + tid], s_sq[tid]);
    }
}

// ---------------- GEMM layer2: HFMA2 (R16, proven) ----------------
#define L2G_SMEM (2 * 32 * 136 * 2 + 2 * 32 * 64 * 2)
__global__ __launch_bounds__(256) void k_gemm_l2(const float* __restrict__ b2) {
    extern __shared__ unsigned char sml2raw[];
    unsigned short* As0 = (unsigned short*)sml2raw;
    unsigned short* As1 = As0 + 32 * 136;
    unsigned short* Bs0 = As1 + 32 * 136;
    unsigned short* Bs1 = Bs0 + 32 * 64;
    __shared__ float s_sum[64], s_sq[64];
    int tid = threadIdx.x;
    if (tid < 64) { s_sum[tid] = 0.f; s_sq[tid] = 0.f; }
    int n0 = blockIdx.x * 128;
    int tn = tid >> 4, to = tid & 15;
    int kq = tid & 7, rr = tid >> 3;

    float acc[8][4];
    #pragma unroll
    for (int m = 0; m < 8; m++)
        #pragma unroll
        for (int c = 0; c < 4; c++) acc[m][c] = 0.f;

    uint2 pa[4];
    uint4 pb;

    auto load_stage = [&](int s) {
        #pragma unroll
        for (int it = 0; it < 4; it++) {
            int row = it * 32 + rr;
            int gn = n0 + row;
            uint2 raw = make_uint2(0u, 0u);
            if (gn < NN) {
                const __half* src = (s < 8)
                    ? g_T2 + (size_t)gn * 256 + s * 32 + kq * 4
                    : g_h1nh + (size_t)gn * 32 + kq * 4;
                raw = __ldg((const uint2*)src);
            }
            pa[it] = raw;
        }
        pb = __ldg((const uint4*)(g_W2ph + s * 2048) + tid);
    };
    auto store_stage = [&](unsigned short* Ab, unsigned short* Bb) {
        #pragma unroll
        for (int it = 0; it < 4; it++) {
            int row = it * 32 + rr;
            unsigned lo = pa[it].x, hi = pa[it].y;
            Ab[(kq * 4 + 0) * 136 + row] = (unsigned short)(lo & 0xffff);
            Ab[(kq * 4 + 1) * 136 + row] = (unsigned short)(lo >> 16);
            Ab[(kq * 4 + 2) * 136 + row] = (unsigned short)(hi & 0xffff);
            Ab[(kq * 4 + 3) * 136 + row] = (unsigned short)(hi >> 16);
        }
        *((uint4*)Bb + tid) = pb;
    };

    load_stage(0);
    store_stage(As0, Bs0);
    __syncthreads();

    for (int s = 0; s < 9; s++) {
        int buf = s & 1;
        if (s < 8) load_stage(s + 1);
        const unsigned short* Ab = buf ? As1 : As0;
        const unsigned short* Bb = buf ? Bs1 : Bs0;

        __half2 acc2[8][2];
        #pragma unroll
        for (int m = 0; m < 8; m++) {
            acc2[m][0] = __float2half2_rn(0.f);
            acc2[m][1] = __float2half2_rn(0.f);
        }
        #pragma unroll
        for (int k = 0; k < 32; k++) {
            uint4 a8 = *(const uint4*)(Ab + k * 136 + tn * 8);
            uint2 b4 = *(const uint2*)(Bb + k * 64 + to * 4);
            __half2 b01 = *(__half2*)&b4.x;
            __half2 b23 = *(__half2*)&b4.y;
            __half2 h01 = *(__half2*)&a8.x;
            __half2 h23 = *(__half2*)&a8.y;
            __half2 h45 = *(__half2*)&a8.z;
            __half2 h67 = *(__half2*)&a8.w;
            __half2 am;
            am = __low2half2(h01);
            acc2[0][0] = __hfma2(am, b01, acc2[0][0]);
            acc2[0][1] = __hfma2(am, b23, acc2[0][1]);
            am = __high2half2(h01);
            acc2[1][0] = __hfma2(am, b01, acc2[1][0]);
            acc2[1][1] = __hfma2(am, b23, acc2[1][1]);
            am = __low2half2(h23);
            acc2[2][0] = __hfma2(am, b01, acc2[2][0]);
            acc2[2][1] = __hfma2(am, b23, acc2[2][1]);
            am = __high2half2(h23);
            acc2[3][0] = __hfma2(am, b01, acc2[3][0]);
            acc2[3][1] = __hfma2(am, b23, acc2[3][1]);
            am = __low2half2(h45);
            acc2[4][0] = __hfma2(am, b01, acc2[4][0]);
            acc2[4][1] = __hfma2(am, b23, acc2[4][1]);
            am = __high2half2(h45);
            acc2[5][0] = __hfma2(am, b01, acc2[5][0]);
            acc2[5][1] = __hfma2(am, b23, acc2[5][1]);
            am = __low2half2(h67);
            acc2[6][0] = __hfma2(am, b01, acc2[6][0]);
            acc2[6][1] = __hfma2(am, b23, acc2[6][1]);
            am = __high2half2(h67);
            acc2[7][0] = __hfma2(am, b01, acc2[7][0]);
            acc2[7][1] = __hfma2(am, b23, acc2[7][1]);
        }
        #pragma unroll
        for (int m = 0; m < 8; m++) {
            float2 f0 = __half22float2(acc2[m][0]);
            float2 f1 = __half22float2(acc2[m][1]);
            acc[m][0] += f0.x; acc[m][1] += f0.y;
            acc[m][2] += f1.x; acc[m][3] += f1.y;
        }
        if (s < 8) store_stage(buf ? As0 : As1, buf ? Bs0 : Bs1);
        __syncthreads();
    }

    float bv[4];
    #pragma unroll
    for (int c = 0; c < 4; c++) bv[c] = __ldg(b2 + to * 4 + c);
    float ls[4] = {0, 0, 0, 0}, lq[4] = {0, 0, 0, 0};
    #pragma unroll
    for (int m = 0; m < 8; m++) {
        int gn = n0 + tn * 8 + m;
        if (gn < NN) {
            float h0 = acc[m][0] + bv[0], h1 = acc[m][1] + bv[1];
            float h2 = acc[m][2] + bv[2], h3 = acc[m][3] + bv[3];
            *(uint2*)(g_h2h + (size_t)gn * 64 + to * 4) = pack4h(h0, h1, h2, h3);
            ls[0] += h0; ls[1] += h1; ls[2] += h2; ls[3] += h3;
            lq[0] += h0 * h0; lq[1] += h1 * h1; lq[2] += h2 * h2; lq[3] += h3 * h3;
        }
    }
    #pragma unroll
    for (int c = 0; c < 4; c++) {
        atomicAdd(&s_sum[to * 4 + c], ls[c]);
        atomicAdd(&s_sq [to * 4 + c], lq[c]);
    }
    __syncthreads();
    if (tid < 64) {
        atomicAdd(&g_stat2[tid],      s_sum[tid]);
        atomicAdd(&g_stat2[64 + tid], s_sq[tid]);
    }
}

// ---------------- BN1 apply + relu -> h1nh (fp16 in/out) ----------------
__global__ void k_bn1(const float* __restrict__ g1, const float* __restrict__ be1) {
    int idx = blockIdx.x * blockDim.x + threadIdx.x;
    if (idx >= NN * 8) return;
    int n = idx >> 3, q = idx & 7;
    const float invN = 1.0f / (float)NN;
    float4 h = unpack4h(__ldg((const uint2*)(g_h1h + (size_t)n * 32 + q * 4)));
    float v[4];
    float* hv = (float*)&h;
    #pragma unroll
    for (int j = 0; j < 4; j++) {
        int c = q * 4 + j;
        float mu = g_stat1[c] * invN;
        float var = g_stat1[32 + c] * invN - mu * mu;
        float rs = rsqrtf(var + EPSV);
        v[j] = fmaxf((hv[j] - mu) * rs * __ldg(g1 + c) + __ldg(be1 + c), 0.f);
    }
    *(uint2*)(g_h1nh + (size_t)n * 32 + q * 4) = pack4h(v[0], v[1], v[2], v[3]);
}

// ---------------- BN2 apply + relu + pooling (4-node runs, fp16 in) ---------
__global__ void k_bn2pool(const float* __restrict__ g2, const float* __restrict__ be2,
                          const int* __restrict__ batch) {
    int idx = blockIdx.x * blockDim.x + threadIdx.x;
    if (idx >= NN * 4) return;
    int nq = idx >> 4, q = idx & 15;
    int n0 = nq * 4;
    const float invN = 1.0f / (float)NN;

    float4 hv[4];
    #pragma unroll
    for (int m = 0; m < 4; m++)
        hv[m] = unpack4h(__ldg((const uint2*)(g_h2h + (size_t)(n0 + m) * 64 + q * 4)));

    float mu[4], rsg[4], ba[4];
    #pragma unroll
    for (int j = 0; j < 4; j++) {
        int c = q * 4 + j;
        float m2 = g_stat2[c] * invN;
        float var = g_stat2[64 + c] * invN - m2 * m2;
        mu[j] = m2;
        rsg[j] = rsqrtf(var + EPSV) * __ldg(g2 + c);
        ba[j] = __ldg(be2 + c);
    }
    float v[4][4];
    #pragma unroll
    for (int m = 0; m < 4; m++) {
        float* hm = (float*)&hv[m];
        #pragma unroll
        for (int j = 0; j < 4; j++)
            v[m][j] = fmaxf((hm[j] - mu[j]) * rsg[j] + ba[j], 0.f);
    }
    int b0 = batch[n0], b3 = batch[n0 + 3];
    if (b0 == b3) {
        red_v4(g_pooled + (size_t)b0 * 64 + q * 4,
               make_float4(v[0][0] + v[1][0] + v[2][0] + v[3][0],
                           v[0][1] + v[1][1] + v[2][1] + v[3][1],
                           v[0][2] + v[1][2] + v[2][2] + v[3][2],
                           v[0][3] + v[1][3] + v[2][3] + v[3][3]));
        if (q == 0) atomicAdd(&g_cnt[b0], 4.0f);
    } else {
        int b1 = batch[n0 + 1], b2i = batch[n0 + 2];
        if (b0 == b1) {
            red_v4(g_pooled + (size_t)b0 * 64 + q * 4,
                   make_float4(v[0][0] + v[1][0], v[0][1] + v[1][1],
                               v[0][2] + v[1][2], v[0][3] + v[1][3]));
            if (q == 0) atomicAdd(&g_cnt[b0], 2.0f);
        } else {
            red_v4(g_pooled + (size_t)b0 * 64 + q * 4,
                   make_float4(v[0][0], v[0][1], v[0][2], v[0][3]));
            red_v4(g_pooled + (size_t)b1 * 64 + q * 4,
                   make_float4(v[1][0], v[1][1], v[1][2], v[1][3]));
            if (q == 0) { atomicAdd(&g_cnt[b0], 1.0f); atomicAdd(&g_cnt[b1], 1.0f); }
        }
        if (b2i == b3) {
            red_v4(g_pooled + (size_t)b2i * 64 + q * 4,
                   make_float4(v[2][0] + v[3][0], v[2][1] + v[3][1],
                               v[2][2] + v[3][2], v[2][3] + v[3][3]));
            if (q == 0) atomicAdd(&g_cnt[b2i], 2.0f);
        } else {
            red_v4(g_pooled + (size_t)b2i * 64 + q * 4,
                   make_float4(v[2][0], v[2][1], v[2][2], v[2][3]));
            red_v4(g_pooled + (size_t)b3 * 64 + q * 4,
                   make_float4(v[3][0], v[3][1], v[3][2], v[3][3]));
            if (q == 0) { atomicAdd(&g_cnt[b2i], 1.0f); atomicAdd(&g_cnt[b3], 1.0f); }
        }
    }
}

// ---------------- final MLP ----------------
__global__ __launch_bounds__(128) void k_fc(const float* __restrict__ bf1,
                                            const float* __restrict__ bf2,
                                            float* __restrict__ out) {
    __shared__ float pm[8][64];
    __shared__ float hid[8][128];
    int tid = threadIdx.x;
    int g0 = blockIdx.x * 8;
    for (int t = tid; t < 512; t += 128) {
        int gg = t >> 6, i = t & 63;
        int g = g0 + gg;
        pm[gg][i] = g_pooled[g * 64 + i] / fmaxf(g_cnt[g], 1.0f);
    }
    __syncthreads();

    float acc[8];
    float b = bf1[tid];
    #pragma unroll
    for (int gg = 0; gg < 8; gg++) acc[gg] = b;
    for (int i = 0; i < 64; i++) {
        float w = g_Wt1[i * 128 + tid];
        #pragma unroll
        for (int gg = 0; gg < 8; gg++) acc[gg] += w * pm[gg][i];
    }
    #pragma unroll
    for (int gg = 0; gg < 8; gg++) hid[gg][tid] = fmaxf(acc[gg], 0.f);
    __syncthreads();

    float b2v = bf2[tid];
    #pragma unroll
    for (int gg = 0; gg < 8; gg++) acc[gg] = b2v;
    for (int i = 0; i < 128; i++) {
        float w = g_Wt2[i * 128 + tid];
        #pragma unroll
        for (int gg = 0; gg < 8; gg++) acc[gg] += w * hid[gg][i];
    }
    #pragma unroll
    for (int gg = 0; gg < 8; gg++) {
        int g = g0 + gg;
        if (tid < 64) out[g * 64 + tid] = acc[gg];
        else          out[NG * 64 + g * 64 + (tid - 64)] = acc[gg];
    }
}

// ---------------- launch ----------------
extern "C" void kernel_launch(void* const* d_in, const int* in_sizes, int n_in,
                              void* d_out, int out_size) {
    const float* x    = (const float*)d_in[0];
    const int*   ei   = (const int*)  d_in[1];
    const float* ea   = (const float*)d_in[2];
    const int*   batch= (const int*)  d_in[3];
    const float* We1  = (const float*)d_in[4];
    const float* b1   = (const float*)d_in[5];
    const float* Wr1  = (const float*)d_in[6];
    const float* g1   = (const float*)d_in[7];
    const float* be1  = (const float*)d_in[8];
    const float* We2  = (const float*)d_in[9];
    const float* b2   = (const float*)d_in[10];
    const float* Wr2  = (const float*)d_in[11];
    const float* g2   = (const float*)d_in[12];
    const float* be2  = (const float*)d_in[13];
    const float* Wf1  = (const float*)d_in[14];
    const float* bf1  = (const float*)d_in[15];
    const float* Wf2  = (const float*)d_in[16];
    const float* bf2  = (const float*)d_in[17];
    float* out = (float*)d_out;

    static int attr_set = 0;
    if (!attr_set) {
        cudaFuncSetAttribute(k_gemm_l2, cudaFuncAttributeMaxDynamicSharedMemorySize,
                             L2G_SMEM);
        attr_set = 1;
    }

    k_setup<<<256, 256>>>(We1, Wr1, We2, Wr2, Wf1, Wf2);
    k_degs<<<(NE + 255) / 256, 256>>>(ei);
    k_scan_a<<<SCAN_NB, 256>>>();
    k_scan_c<<<SCAN_NB, 256>>>();
    k_fill<<<(NE + 255) / 256, 256>>>(ei, ea);
    k_gath1<<<(NN * 4 + 255) / 256, 256>>>(x);
    k_gemm_l1<<<(NN + 127) / 128, 128>>>(x, b1);
    k_bn1<<<(NN * 8 + 255) / 256, 256>>>(g1, be1);
    k_gath2<<<(NN * 8 + 255) / 256, 256>>>();
    k_gemm_l2<<<(NN + 127) / 128, 256, L2G_SMEM>>>(b2);
    k_bn2pool<<<(NN * 4 + 255) / 256, 256>>>(g2, be2, batch);
    k_fc<<<NG / 8, 128>>>(bf1, bf2, out);
}